// round 2
// baseline (speedup 1.0000x reference)
#include <cuda_runtime.h>
#include <math.h>

#define T_TOK 4096
#define D_MODEL 2048
#define S_SEQ 2048
#define NH 16
#define NKV 4
#define HDIM 128
#define NE 8
#define NF 1024

// ---------------- scratch (static device allocations; no cudaMalloc) ----------------
__device__ float g_h  [T_TOK * D_MODEL];
__device__ float g_q  [T_TOK * NH * HDIM];
__device__ float g_k  [T_TOK * NKV * HDIM];
__device__ float g_v  [T_TOK * NKV * HDIM];
__device__ float g_o  [T_TOK * NH * HDIM];
__device__ float g_x2 [T_TOK * D_MODEL];
__device__ float g_h2 [T_TOK * D_MODEL];
__device__ float g_act[T_TOK * 2 * NF];
__device__ int   g_toklist[NE * T_TOK];
__device__ float g_tokgate[NE * T_TOK];
__device__ int   g_expcnt[NE];

// ---------------- rmsnorm over rows of length D_MODEL ----------------
__global__ void rmsnorm_kernel(const float* __restrict__ x, const float* __restrict__ w,
                               float* __restrict__ out) {
    int row = blockIdx.x;
    int tid = threadIdx.x;  // 256
    const float* xr = x + (size_t)row * D_MODEL;
    float xv[8];
    float ss = 0.f;
#pragma unroll
    for (int i = 0; i < 8; i++) {
        xv[i] = xr[tid + i * 256];
        ss += xv[i] * xv[i];
    }
#pragma unroll
    for (int o = 16; o > 0; o >>= 1) ss += __shfl_xor_sync(0xffffffffu, ss, o);
    __shared__ float sred[8];
    if ((tid & 31) == 0) sred[tid >> 5] = ss;
    __syncthreads();
    float tot = 0.f;
#pragma unroll
    for (int i = 0; i < 8; i++) tot += sred[i];
    float rs = rsqrtf(tot / (float)D_MODEL + 1e-6f);
    float* orow = out + (size_t)row * D_MODEL;
#pragma unroll
    for (int i = 0; i < 8; i++) {
        int d = tid + i * 256;
        orow[d] = xv[i] * rs * w[d];
    }
}

// ---------------- SGEMM: C[M,N] = A[M,K] @ B[N,K]^T (both K-contiguous) ----------------
// BM=BN=128, BK=8, 256 threads, 8x8 microtile.
// resid (optional): C += resid  (row stride N). aux (optional): duplicate write.
__global__ __launch_bounds__(256) void sgemm_nt(const float* __restrict__ A,
                                                const float* __restrict__ B,
                                                float* __restrict__ C, int N, int K,
                                                const float* __restrict__ resid,
                                                float* __restrict__ aux) {
    __shared__ float As[8][128];
    __shared__ float Bs[8][128];
    int m0 = blockIdx.y * 128, n0 = blockIdx.x * 128;
    int tid = threadIdx.x;
    int ty = tid >> 4, tx = tid & 15;
    int lrow = tid >> 1, lk4 = (tid & 1) * 4;
    const float* Ald = A + (size_t)(m0 + lrow) * K + lk4;
    const float* Bld = B + (size_t)(n0 + lrow) * K + lk4;
    float acc[8][8];
#pragma unroll
    for (int i = 0; i < 8; i++)
#pragma unroll
        for (int j = 0; j < 8; j++) acc[i][j] = 0.f;

    for (int k0 = 0; k0 < K; k0 += 8) {
        float4 av = *(const float4*)(Ald + k0);
        float4 bv = *(const float4*)(Bld + k0);
        __syncthreads();
        As[lk4 + 0][lrow] = av.x; As[lk4 + 1][lrow] = av.y;
        As[lk4 + 2][lrow] = av.z; As[lk4 + 3][lrow] = av.w;
        Bs[lk4 + 0][lrow] = bv.x; Bs[lk4 + 1][lrow] = bv.y;
        Bs[lk4 + 2][lrow] = bv.z; Bs[lk4 + 3][lrow] = bv.w;
        __syncthreads();
#pragma unroll
        for (int kk = 0; kk < 8; kk++) {
            float a[8], b[8];
#pragma unroll
            for (int i = 0; i < 8; i++) a[i] = As[kk][ty * 8 + i];
#pragma unroll
            for (int j = 0; j < 8; j++) b[j] = Bs[kk][tx * 8 + j];
#pragma unroll
            for (int i = 0; i < 8; i++)
#pragma unroll
                for (int j = 0; j < 8; j++) acc[i][j] += a[i] * b[j];
        }
    }
#pragma unroll
    for (int i = 0; i < 8; i++) {
        int r = m0 + ty * 8 + i;
        size_t base = (size_t)r * N + n0 + tx * 8;
#pragma unroll
        for (int j = 0; j < 8; j++) {
            float v = acc[i][j];
            if (resid) v += resid[base + j];
            C[base + j] = v;
            if (aux) aux[base + j] = v;
        }
    }
}

// ---------------- per-head rmsnorm + RoPE (in place) ----------------
__global__ void qknorm_rope(float* __restrict__ data, const float* __restrict__ w, int nheads) {
    int gb = blockIdx.x;
    int t = gb / nheads;
    int h = gb - t * nheads;
    int tid = threadIdx.x;  // 128
    float* ptr = data + ((size_t)t * nheads + h) * HDIM;
    float v = ptr[tid];
    float ss = v * v;
#pragma unroll
    for (int o = 16; o > 0; o >>= 1) ss += __shfl_xor_sync(0xffffffffu, ss, o);
    __shared__ float sred[4];
    __shared__ float buf[HDIM];
    if ((tid & 31) == 0) sred[tid >> 5] = ss;
    __syncthreads();
    float tot = sred[0] + sred[1] + sred[2] + sred[3];
    float rs = rsqrtf(tot / 128.f + 1e-6f);
    buf[tid] = v * rs * w[tid];
    __syncthreads();
    int s = t & (S_SEQ - 1);
    int i = tid & 63;
    // inv_freq = 10000^(-i/64) = exp2(-i * log2(10000)/64)
    float fi = exp2f(-(float)i * 0.20762050592154265f);
    float ang = (float)s * fi;
    float sn, cs;
    sincosf(ang, &sn, &cs);
    float x1 = buf[i];
    float x2 = buf[i + 64];
    float outv = (tid < 64) ? (x1 * cs - x2 * sn) : (x1 * sn + x2 * cs);
    ptr[tid] = outv;
}

// ---------------- causal flash attention ----------------
// grid (32, NH, B); 128 threads. BM=64 query rows (2 threads/row), BN=32 key tile.
// K/V smem layout: two half-sections padded by 1 float4 to avoid bank collision.
__global__ __launch_bounds__(128) void attn_kernel(const float* __restrict__ Q,
                                                   const float* __restrict__ Kg,
                                                   const float* __restrict__ Vg,
                                                   float* __restrict__ O) {
    __shared__ float4 Ks[2 * 513];
    __shared__ float4 Vs[2 * 513];
    int qb = 31 - (int)blockIdx.x;  // heavy blocks launch first
    int h = blockIdx.y, b = blockIdx.z;
    int tid = threadIdx.x;
    int r = tid >> 1, half = tid & 1;
    int kvh = h >> 2;
    int qrow = qb * 64 + r;
    const float scale = 0.0883883476483184f;  // 1/sqrt(128)
    float4 Qr[16];
    {
        const float* qp = Q + (((size_t)(b * S_SEQ + qrow) * NH + h) * HDIM + half * 64);
#pragma unroll
        for (int i = 0; i < 16; i++) {
            float4 v = *(const float4*)(qp + i * 4);
            v.x *= scale; v.y *= scale; v.z *= scale; v.w *= scale;
            Qr[i] = v;
        }
    }
    float4 Oa[16];
#pragma unroll
    for (int i = 0; i < 16; i++) Oa[i] = make_float4(0.f, 0.f, 0.f, 0.f);
    float mval = -1e30f, l = 0.f;
    int nkb = qb * 2 + 2;
    for (int kb = 0; kb < nkb; kb++) {
        __syncthreads();
#pragma unroll
        for (int i = 0; i < 8; i++) {
            int f4 = i * 128 + tid;
            int row = f4 >> 5, c4 = f4 & 31;
            size_t goff = (((size_t)(b * S_SEQ + kb * 32 + row) * NKV + kvh) * HDIM + c4 * 4);
            int sm = (c4 >> 4) * 513 + row * 16 + (c4 & 15);
            Ks[sm] = *(const float4*)(Kg + goff);
            Vs[sm] = *(const float4*)(Vg + goff);
        }
        __syncthreads();
        float s[32];
        bool masked = (kb >= qb * 2);
        const float4* kbase = &Ks[half * 513];
#pragma unroll
        for (int j = 0; j < 32; j++) {
            const float4* kr = kbase + j * 16;
            float p = 0.f;
#pragma unroll
            for (int dd = 0; dd < 16; dd++) {
                float4 kv = kr[dd];
                float4 qv = Qr[dd];
                p += qv.x * kv.x; p += qv.y * kv.y;
                p += qv.z * kv.z; p += qv.w * kv.w;
            }
            p += __shfl_xor_sync(0xffffffffu, p, 1);
            if (masked && (kb * 32 + j > qrow)) p = -1e30f;
            s[j] = p;
        }
        float mt = s[0];
#pragma unroll
        for (int j = 1; j < 32; j++) mt = fmaxf(mt, s[j]);
        float m_new = fmaxf(mval, mt);
        float sc = __expf(mval - m_new);
        l *= sc;
#pragma unroll
        for (int i = 0; i < 16; i++) {
            Oa[i].x *= sc; Oa[i].y *= sc; Oa[i].z *= sc; Oa[i].w *= sc;
        }
#pragma unroll
        for (int j = 0; j < 32; j++) {
            float pj = __expf(s[j] - m_new);
            l += pj;
            s[j] = pj;
        }
        const float4* vbase = &Vs[half * 513];
#pragma unroll
        for (int j = 0; j < 32; j++) {
            float pj = s[j];
            const float4* vr = vbase + j * 16;
#pragma unroll
            for (int dd = 0; dd < 16; dd++) {
                float4 vv = vr[dd];
                Oa[dd].x += pj * vv.x; Oa[dd].y += pj * vv.y;
                Oa[dd].z += pj * vv.z; Oa[dd].w += pj * vv.w;
            }
        }
        mval = m_new;
    }
    float inv = 1.f / l;
    float* op = O + ((size_t)(b * S_SEQ + qrow) * (NH * HDIM) + h * HDIM + half * 64);
#pragma unroll
    for (int i = 0; i < 16; i++) {
        float4 v = Oa[i];
        v.x *= inv; v.y *= inv; v.z *= inv; v.w *= inv;
        *(float4*)(op + i * 4) = v;
    }
}

// ---------------- router: softmax over 8 experts, top-2, build expert lists ----------------
__global__ void zero_cnt_kernel() { g_expcnt[threadIdx.x] = 0; }

__global__ void router_kernel(const float* __restrict__ h2, const float* __restrict__ wr) {
    int t = blockIdx.x;
    int tid = threadIdx.x;  // 256
    float p[8];
#pragma unroll
    for (int e = 0; e < 8; e++) p[e] = 0.f;
#pragma unroll
    for (int i = 0; i < 8; i++) {
        int d = tid + i * 256;
        float hv = h2[(size_t)t * D_MODEL + d];
#pragma unroll
        for (int e = 0; e < 8; e++) p[e] += hv * wr[e * D_MODEL + d];
    }
    __shared__ float red[8][256];
#pragma unroll
    for (int e = 0; e < 8; e++) red[e][tid] = p[e];
    __syncthreads();
    for (int stp = 128; stp > 0; stp >>= 1) {
        if (tid < stp) {
#pragma unroll
            for (int e = 0; e < 8; e++) red[e][tid] += red[e][tid + stp];
        }
        __syncthreads();
    }
    if (tid == 0) {
        float lg[8];
        float m = -1e30f;
#pragma unroll
        for (int e = 0; e < 8; e++) { lg[e] = red[e][0]; m = fmaxf(m, lg[e]); }
        float pr[8];
#pragma unroll
        for (int e = 0; e < 8; e++) pr[e] = __expf(lg[e] - m);
        int i1 = 0;
#pragma unroll
        for (int e = 1; e < 8; e++) if (pr[e] > pr[i1]) i1 = e;
        int i2 = (i1 == 0) ? 1 : 0;
#pragma unroll
        for (int e = 0; e < 8; e++) if (e != i1 && pr[e] > pr[i2]) i2 = e;
        float v1 = pr[i1], v2 = pr[i2];
        float denom = v1 + v2;
        float gate1 = v1 / denom, gate2 = v2 / denom;
        int pos1 = atomicAdd(&g_expcnt[i1], 1);
        g_toklist[i1 * T_TOK + pos1] = t * 2;
        g_tokgate[i1 * T_TOK + pos1] = gate1;
        int pos2 = atomicAdd(&g_expcnt[i2], 1);
        g_toklist[i2 * T_TOK + pos2] = t * 2 + 1;
        g_tokgate[i2 * T_TOK + pos2] = gate2;
    }
}

// ---------------- grouped MoE gate/up GEMM + fused SiLU ----------------
// BM=128 (gathered rows), BN=64 (over F), BK=8. 256 threads, 8x4 microtile x2 mats.
__global__ __launch_bounds__(256) void moe_act_kernel(const float* __restrict__ h2,
                                                      const float* __restrict__ wg,
                                                      const float* __restrict__ wu,
                                                      float* __restrict__ act) {
    int e = blockIdx.z;
    int cnt = g_expcnt[e];
    int mbase = blockIdx.x * 128;
    if (mbase >= cnt) return;
    int nbase = blockIdx.y * 64;

    __shared__ float As[8][128];
    __shared__ float Bg[8][64];
    __shared__ float Bu[8][64];
    __shared__ int rows_s[128];
    __shared__ float gate_s[128];

    int tid = threadIdx.x;
    if (tid < 128) {
        int idx = mbase + tid;
        if (idx >= cnt) idx = cnt - 1;
        rows_s[tid] = g_toklist[e * T_TOK + idx];
        gate_s[tid] = g_tokgate[e * T_TOK + idx];
    }
    __syncthreads();

    int lrow = tid >> 1, lk4 = (tid & 1) * 4;
    const float* Aptr = h2 + (size_t)(rows_s[lrow] >> 1) * D_MODEL + lk4;
    int bl = tid & 127;
    int brow = bl >> 1, bk4 = (bl & 1) * 4;
    const float* Bptr = ((tid < 128) ? wg : wu) + (size_t)e * NF * D_MODEL +
                        (size_t)(nbase + brow) * D_MODEL + bk4;
    float* Bsm = (tid < 128) ? &Bg[0][0] : &Bu[0][0];

    int ty = tid >> 4, tx = tid & 15;
    float accG[8][4], accU[8][4];
#pragma unroll
    for (int i = 0; i < 8; i++)
#pragma unroll
        for (int j = 0; j < 4; j++) { accG[i][j] = 0.f; accU[i][j] = 0.f; }

    for (int k0 = 0; k0 < D_MODEL; k0 += 8) {
        float4 av = *(const float4*)(Aptr + k0);
        float4 bv = *(const float4*)(Bptr + k0);
        __syncthreads();
        As[lk4 + 0][lrow] = av.x; As[lk4 + 1][lrow] = av.y;
        As[lk4 + 2][lrow] = av.z; As[lk4 + 3][lrow] = av.w;
        Bsm[(bk4 + 0) * 64 + brow] = bv.x; Bsm[(bk4 + 1) * 64 + brow] = bv.y;
        Bsm[(bk4 + 2) * 64 + brow] = bv.z; Bsm[(bk4 + 3) * 64 + brow] = bv.w;
        __syncthreads();
#pragma unroll
        for (int kk = 0; kk < 8; kk++) {
            float a[8], bg[4], bu[4];
#pragma unroll
            for (int i = 0; i < 8; i++) a[i] = As[kk][ty * 8 + i];
#pragma unroll
            for (int j = 0; j < 4; j++) { bg[j] = Bg[kk][tx * 4 + j]; bu[j] = Bu[kk][tx * 4 + j]; }
#pragma unroll
            for (int i = 0; i < 8; i++)
#pragma unroll
                for (int j = 0; j < 4; j++) {
                    accG[i][j] += a[i] * bg[j];
                    accU[i][j] += a[i] * bu[j];
                }
        }
    }
#pragma unroll
    for (int i = 0; i < 8; i++) {
        int rloc = ty * 8 + i;
        if (mbase + rloc < cnt) {
            int entry = rows_s[rloc];
            float gte = gate_s[rloc];
            size_t base = (size_t)entry * NF + nbase + tx * 4;
#pragma unroll
            for (int j = 0; j < 4; j++) {
                float gv = accG[i][j];
                float uv = accU[i][j];
                float sig = 1.f / (1.f + __expf(-gv));
                act[base + j] = gte * gv * sig * uv;
            }
        }
    }
}

// ---------------- grouped MoE down GEMM, atomicAdd into output ----------------
__global__ __launch_bounds__(256) void moe_down_kernel(const float* __restrict__ act,
                                                       const float* __restrict__ wd,
                                                       float* __restrict__ out) {
    int e = blockIdx.z;
    int cnt = g_expcnt[e];
    int mbase = blockIdx.x * 128;
    if (mbase >= cnt) return;
    int nbase = blockIdx.y * 64;

    __shared__ float As[8][128];
    __shared__ float Bs[8][64];
    __shared__ int rows_s[128];

    int tid = threadIdx.x;
    if (tid < 128) {
        int idx = mbase + tid;
        if (idx >= cnt) idx = cnt - 1;
        rows_s[tid] = g_toklist[e * T_TOK + idx];
    }
    __syncthreads();

    int lrow = tid >> 1, lk4 = (tid & 1) * 4;
    const float* Aptr = act + (size_t)rows_s[lrow] * NF + lk4;
    int brow = (tid & 127) >> 1, bk4 = (tid & 1) * 4;
    const float* Bptr = wd + (size_t)e * D_MODEL * NF + (size_t)(nbase + brow) * NF + bk4;
    bool doB = (tid < 128);

    int ty = tid >> 4, tx = tid & 15;
    float acc[8][4];
#pragma unroll
    for (int i = 0; i < 8; i++)
#pragma unroll
        for (int j = 0; j < 4; j++) acc[i][j] = 0.f;

    for (int k0 = 0; k0 < NF; k0 += 8) {
        float4 av = *(const float4*)(Aptr + k0);
        float4 bv = make_float4(0.f, 0.f, 0.f, 0.f);
        if (doB) bv = *(const float4*)(Bptr + k0);
        __syncthreads();
        As[lk4 + 0][lrow] = av.x; As[lk4 + 1][lrow] = av.y;
        As[lk4 + 2][lrow] = av.z; As[lk4 + 3][lrow] = av.w;
        if (doB) {
            Bs[bk4 + 0][brow] = bv.x; Bs[bk4 + 1][brow] = bv.y;
            Bs[bk4 + 2][brow] = bv.z; Bs[bk4 + 3][brow] = bv.w;
        }
        __syncthreads();
#pragma unroll
        for (int kk = 0; kk < 8; kk++) {
            float a[8], b[4];
#pragma unroll
            for (int i = 0; i < 8; i++) a[i] = As[kk][ty * 8 + i];
#pragma unroll
            for (int j = 0; j < 4; j++) b[j] = Bs[kk][tx * 4 + j];
#pragma unroll
            for (int i = 0; i < 8; i++)
#pragma unroll
                for (int j = 0; j < 4; j++) acc[i][j] += a[i] * b[j];
        }
    }
#pragma unroll
    for (int i = 0; i < 8; i++) {
        int rloc = ty * 8 + i;
        if (mbase + rloc < cnt) {
            int tok = rows_s[rloc] >> 1;
            size_t base = (size_t)tok * D_MODEL + nbase + tx * 4;
#pragma unroll
            for (int j = 0; j < 4; j++) atomicAdd(&out[base + j], acc[i][j]);
        }
    }
}

// ---------------- host launch ----------------
extern "C" void kernel_launch(void* const* d_in, const int* in_sizes, int n_in,
                              void* d_out, int out_size) {
    const float* x          = (const float*)d_in[0];
    const float* wattn_norm = (const float*)d_in[1];
    const float* wq         = (const float*)d_in[2];
    const float* wk         = (const float*)d_in[3];
    const float* wv         = (const float*)d_in[4];
    const float* wq_norm    = (const float*)d_in[5];
    const float* wk_norm    = (const float*)d_in[6];
    const float* wattn_out  = (const float*)d_in[7];
    const float* wffn_norm  = (const float*)d_in[8];
    const float* w_router   = (const float*)d_in[9];
    const float* w_gate     = (const float*)d_in[10];
    const float* w_up       = (const float*)d_in[11];
    const float* w_down     = (const float*)d_in[12];
    float* out = (float*)d_out;

    float *p_h, *p_q, *p_k, *p_v, *p_o, *p_x2, *p_h2, *p_act;
    cudaGetSymbolAddress((void**)&p_h, g_h);
    cudaGetSymbolAddress((void**)&p_q, g_q);
    cudaGetSymbolAddress((void**)&p_k, g_k);
    cudaGetSymbolAddress((void**)&p_v, g_v);
    cudaGetSymbolAddress((void**)&p_o, g_o);
    cudaGetSymbolAddress((void**)&p_x2, g_x2);
    cudaGetSymbolAddress((void**)&p_h2, g_h2);
    cudaGetSymbolAddress((void**)&p_act, g_act);

    // 1. h = rmsnorm(x, wattn_norm)
    rmsnorm_kernel<<<T_TOK, 256>>>(x, wattn_norm, p_h);
    // 2. q/k/v projections (NT GEMM)
    sgemm_nt<<<dim3(16, 32), 256>>>(p_h, wq, p_q, NH * HDIM, D_MODEL, nullptr, nullptr);
    sgemm_nt<<<dim3(4, 32), 256>>>(p_h, wk, p_k, NKV * HDIM, D_MODEL, nullptr, nullptr);
    sgemm_nt<<<dim3(4, 32), 256>>>(p_h, wv, p_v, NKV * HDIM, D_MODEL, nullptr, nullptr);
    // 3. per-head rmsnorm + rope
    qknorm_rope<<<T_TOK * NH, 128>>>(p_q, wq_norm, NH);
    qknorm_rope<<<T_TOK * NKV, 128>>>(p_k, wk_norm, NKV);
    // 4. causal GQA attention
    attn_kernel<<<dim3(32, NH, 2), 128>>>(p_q, p_k, p_v, p_o);
    // 5. out projection + residual; seeds both g_x2 and d_out
    sgemm_nt<<<dim3(16, 32), 256>>>(p_o, wattn_out, p_x2, D_MODEL, NH * HDIM, x, out);
    // 6. h2 = rmsnorm(x2, wffn_norm)
    rmsnorm_kernel<<<T_TOK, 256>>>(p_x2, wffn_norm, p_h2);
    // 7. router + expert gather lists
    zero_cnt_kernel<<<1, NE>>>();
    router_kernel<<<T_TOK, 256>>>(p_h2, w_router);
    // 8. grouped gate/up GEMM + SiLU (gate weight folded in)
    moe_act_kernel<<<dim3(32, 16, NE), 256>>>(p_h2, w_gate, w_up, p_act);
    // 9. grouped down GEMM, scatter-add into d_out
    moe_down_kernel<<<dim3(32, 32, NE), 256>>>(p_act, w_down, out);
}

// round 4
// speedup vs baseline: 1.7595x; 1.7595x over previous
#include <cuda_runtime.h>
#include <cuda_bf16.h>
#include <math.h>
#include <stdint.h>

#define T_TOK 4096
#define D_MODEL 2048
#define S_SEQ 2048
#define NH 16
#define NKV 4
#define HDIM 128
#define NE 8
#define NF 1024
#define LIST_STRIDE (2 * T_TOK)

// ---------------- scratch (static device allocations; no cudaMalloc) ----------------
__device__ float g_q  [T_TOK * NH * HDIM];
__device__ float g_k  [T_TOK * NKV * HDIM];
__device__ float g_v  [T_TOK * NKV * HDIM];
__device__ float g_x2 [T_TOK * D_MODEL];
__device__ float g_h2 [T_TOK * D_MODEL];
__device__ float g_actg[T_TOK * 2 * NF];
__device__ float g_actu[T_TOK * 2 * NF];
__device__ int   g_toklist[NE * LIST_STRIDE];
__device__ float g_entrygate[2 * T_TOK];
__device__ int   g_expcnt[NE];

// bf16 hi/lo split buffers
__device__ __nv_bfloat16 g_h_hi [T_TOK * D_MODEL],  g_h_lo [T_TOK * D_MODEL];
__device__ __nv_bfloat16 g_h2_hi[T_TOK * D_MODEL],  g_h2_lo[T_TOK * D_MODEL];
__device__ __nv_bfloat16 g_o_hi [T_TOK * D_MODEL],  g_o_lo [T_TOK * D_MODEL];
__device__ __nv_bfloat16 g_act_hi[T_TOK * 2 * NF],  g_act_lo[T_TOK * 2 * NF];
__device__ __nv_bfloat16 g_wq_hi[2048 * 2048], g_wq_lo[2048 * 2048];
__device__ __nv_bfloat16 g_wk_hi[512 * 2048],  g_wk_lo[512 * 2048];
__device__ __nv_bfloat16 g_wv_hi[512 * 2048],  g_wv_lo[512 * 2048];
__device__ __nv_bfloat16 g_wo_hi[2048 * 2048], g_wo_lo[2048 * 2048];
__device__ __nv_bfloat16 g_wg_hi[NE * NF * D_MODEL], g_wg_lo[NE * NF * D_MODEL];
__device__ __nv_bfloat16 g_wu_hi[NE * NF * D_MODEL], g_wu_lo[NE * NF * D_MODEL];
__device__ __nv_bfloat16 g_wd_hi[NE * D_MODEL * NF], g_wd_lo[NE * D_MODEL * NF];

// ---------------- PTX helpers (base sm_103-safe: cp.async + ldmatrix + mma.sync) ----
__device__ __forceinline__ uint32_t smem_u32(const void* p) {
    return (uint32_t)__cvta_generic_to_shared(p);
}
__device__ __forceinline__ void cpa16(uint32_t dst, const void* src) {
    asm volatile("cp.async.cg.shared.global [%0], [%1], 16;" :: "r"(dst), "l"(src));
}
__device__ __forceinline__ void cp_commit() { asm volatile("cp.async.commit_group;" ::: "memory"); }
__device__ __forceinline__ void cp_wait2()  { asm volatile("cp.async.wait_group 2;" ::: "memory"); }
__device__ __forceinline__ void cp_wait0()  { asm volatile("cp.async.wait_group 0;" ::: "memory"); }

__device__ __forceinline__ void ldsm_x4(uint32_t r[4], uint32_t addr) {
    asm volatile("ldmatrix.sync.aligned.m8n8.x4.shared.b16 {%0,%1,%2,%3}, [%4];"
                 : "=r"(r[0]), "=r"(r[1]), "=r"(r[2]), "=r"(r[3]) : "r"(addr));
}
__device__ __forceinline__ void mma_16816(float acc[4], const uint32_t a[4], const uint32_t b[2]) {
    asm volatile(
        "mma.sync.aligned.m16n8k16.row.col.f32.bf16.bf16.f32 "
        "{%0,%1,%2,%3}, {%4,%5,%6,%7}, {%8,%9}, {%0,%1,%2,%3};"
        : "+f"(acc[0]), "+f"(acc[1]), "+f"(acc[2]), "+f"(acc[3])
        : "r"(a[0]), "r"(a[1]), "r"(a[2]), "r"(a[3]), "r"(b[0]), "r"(b[1]));
}
__device__ __forceinline__ void split_store(float v, __nv_bfloat16* hp, __nv_bfloat16* lp) {
    __nv_bfloat16 h = __float2bfloat16_rn(v);
    *hp = h;
    *lp = __float2bfloat16_rn(v - __bfloat162float(h));
}

// ---------------- fp32 -> bf16 hi/lo split (weights) ----------------
__global__ void split_kernel(const float* __restrict__ s, __nv_bfloat16* __restrict__ hi,
                             __nv_bfloat16* __restrict__ lo, int n) {
    int i = blockIdx.x * blockDim.x + threadIdx.x;
    int stride = gridDim.x * blockDim.x;
    for (; i < n; i += stride) {
        float v = s[i];
        __nv_bfloat16 h = __float2bfloat16_rn(v);
        hi[i] = h;
        lo[i] = __float2bfloat16_rn(v - __bfloat162float(h));
    }
}

// ---------------- rmsnorm + split ----------------
__global__ void rmsnorm_split(const float* __restrict__ x, const float* __restrict__ w,
                              float* __restrict__ outf, __nv_bfloat16* __restrict__ hi,
                              __nv_bfloat16* __restrict__ lo) {
    int row = blockIdx.x;
    int tid = threadIdx.x;  // 256
    const float* xr = x + (size_t)row * D_MODEL;
    float xv[8];
    float ss = 0.f;
#pragma unroll
    for (int i = 0; i < 8; i++) {
        xv[i] = xr[tid + i * 256];
        ss += xv[i] * xv[i];
    }
#pragma unroll
    for (int o = 16; o > 0; o >>= 1) ss += __shfl_xor_sync(0xffffffffu, ss, o);
    __shared__ float sred[8];
    if ((tid & 31) == 0) sred[tid >> 5] = ss;
    __syncthreads();
    float tot = 0.f;
#pragma unroll
    for (int i = 0; i < 8; i++) tot += sred[i];
    float rs = rsqrtf(tot / (float)D_MODEL + 1e-6f);
    size_t base = (size_t)row * D_MODEL;
#pragma unroll
    for (int i = 0; i < 8; i++) {
        int d = tid + i * 256;
        float v = xv[i] * rs * w[d];
        if (outf) outf[base + d] = v;
        split_store(v, hi + base + d, lo + base + d);
    }
}

// ---------------- per-head rmsnorm + RoPE (in place, fp32) ----------------
__global__ void qknorm_rope(float* __restrict__ data, const float* __restrict__ w, int nheads) {
    int gb = blockIdx.x;
    int t = gb / nheads;
    int h = gb - t * nheads;
    int tid = threadIdx.x;  // 128
    float* ptr = data + ((size_t)t * nheads + h) * HDIM;
    float v = ptr[tid];
    float ss = v * v;
#pragma unroll
    for (int o = 16; o > 0; o >>= 1) ss += __shfl_xor_sync(0xffffffffu, ss, o);
    __shared__ float sred[4];
    __shared__ float buf[HDIM];
    if ((tid & 31) == 0) sred[tid >> 5] = ss;
    __syncthreads();
    float tot = sred[0] + sred[1] + sred[2] + sred[3];
    float rs = rsqrtf(tot / 128.f + 1e-6f);
    buf[tid] = v * rs * w[tid];
    __syncthreads();
    int s = t & (S_SEQ - 1);
    int i = tid & 63;
    float fi = exp2f(-(float)i * 0.20762050592154265f);
    float ang = (float)s * fi;
    float sn, cs;
    sincosf(ang, &sn, &cs);
    float x1 = buf[i];
    float x2 = buf[i + 64];
    float outv = (tid < 64) ? (x1 * cs - x2 * sn) : (x1 * sn + x2 * cs);
    ptr[tid] = outv;
}

// ---------------- causal flash attention (fp32) -> bf16 split output ----------------
__global__ __launch_bounds__(128) void attn_kernel(const float* __restrict__ Q,
                                                   const float* __restrict__ Kg,
                                                   const float* __restrict__ Vg,
                                                   __nv_bfloat16* __restrict__ Ohi,
                                                   __nv_bfloat16* __restrict__ Olo) {
    __shared__ float4 Ks[2 * 513];
    __shared__ float4 Vs[2 * 513];
    int qb = 31 - (int)blockIdx.x;
    int h = blockIdx.y, b = blockIdx.z;
    int tid = threadIdx.x;
    int r = tid >> 1, half = tid & 1;
    int kvh = h >> 2;
    int qrow = qb * 64 + r;
    const float scale = 0.0883883476483184f;
    float4 Qr[16];
    {
        const float* qp = Q + (((size_t)(b * S_SEQ + qrow) * NH + h) * HDIM + half * 64);
#pragma unroll
        for (int i = 0; i < 16; i++) {
            float4 v = *(const float4*)(qp + i * 4);
            v.x *= scale; v.y *= scale; v.z *= scale; v.w *= scale;
            Qr[i] = v;
        }
    }
    float4 Oa[16];
#pragma unroll
    for (int i = 0; i < 16; i++) Oa[i] = make_float4(0.f, 0.f, 0.f, 0.f);
    float mval = -1e30f, l = 0.f;
    int nkb = qb * 2 + 2;
    for (int kb = 0; kb < nkb; kb++) {
        __syncthreads();
#pragma unroll
        for (int i = 0; i < 8; i++) {
            int f4 = i * 128 + tid;
            int row = f4 >> 5, c4 = f4 & 31;
            size_t goff = (((size_t)(b * S_SEQ + kb * 32 + row) * NKV + kvh) * HDIM + c4 * 4);
            int sm = (c4 >> 4) * 513 + row * 16 + (c4 & 15);
            Ks[sm] = *(const float4*)(Kg + goff);
            Vs[sm] = *(const float4*)(Vg + goff);
        }
        __syncthreads();
        float s[32];
        bool masked = (kb >= qb * 2);
        const float4* kbase = &Ks[half * 513];
#pragma unroll
        for (int j = 0; j < 32; j++) {
            const float4* kr = kbase + j * 16;
            float p = 0.f;
#pragma unroll
            for (int dd = 0; dd < 16; dd++) {
                float4 kv = kr[dd];
                float4 qv = Qr[dd];
                p += qv.x * kv.x; p += qv.y * kv.y;
                p += qv.z * kv.z; p += qv.w * kv.w;
            }
            p += __shfl_xor_sync(0xffffffffu, p, 1);
            if (masked && (kb * 32 + j > qrow)) p = -1e30f;
            s[j] = p;
        }
        float mt = s[0];
#pragma unroll
        for (int j = 1; j < 32; j++) mt = fmaxf(mt, s[j]);
        float m_new = fmaxf(mval, mt);
        float sc = __expf(mval - m_new);
        l *= sc;
#pragma unroll
        for (int i = 0; i < 16; i++) {
            Oa[i].x *= sc; Oa[i].y *= sc; Oa[i].z *= sc; Oa[i].w *= sc;
        }
#pragma unroll
        for (int j = 0; j < 32; j++) {
            float pj = __expf(s[j] - m_new);
            l += pj;
            s[j] = pj;
        }
        const float4* vbase = &Vs[half * 513];
#pragma unroll
        for (int j = 0; j < 32; j++) {
            float pj = s[j];
            const float4* vr = vbase + j * 16;
#pragma unroll
            for (int dd = 0; dd < 16; dd++) {
                float4 vv = vr[dd];
                Oa[dd].x += pj * vv.x; Oa[dd].y += pj * vv.y;
                Oa[dd].z += pj * vv.z; Oa[dd].w += pj * vv.w;
            }
        }
        mval = m_new;
    }
    float inv = 1.f / l;
    size_t obase = ((size_t)(b * S_SEQ + qrow) * (NH * HDIM) + h * HDIM + half * 64);
#pragma unroll
    for (int i = 0; i < 16; i++) {
        float4 v = Oa[i];
        v.x *= inv; v.y *= inv; v.z *= inv; v.w *= inv;
        split_store(v.x, Ohi + obase + i * 4 + 0, Olo + obase + i * 4 + 0);
        split_store(v.y, Ohi + obase + i * 4 + 1, Olo + obase + i * 4 + 1);
        split_store(v.z, Ohi + obase + i * 4 + 2, Olo + obase + i * 4 + 2);
        split_store(v.w, Ohi + obase + i * 4 + 3, Olo + obase + i * 4 + 3);
    }
}

// ---------------- router ----------------
__global__ void zero_cnt_kernel() { g_expcnt[threadIdx.x] = 0; }

__global__ void router_kernel(const float* __restrict__ h2, const float* __restrict__ wr) {
    int t = blockIdx.x;
    int tid = threadIdx.x;  // 256
    float p[8];
#pragma unroll
    for (int e = 0; e < 8; e++) p[e] = 0.f;
#pragma unroll
    for (int i = 0; i < 8; i++) {
        int d = tid + i * 256;
        float hv = h2[(size_t)t * D_MODEL + d];
#pragma unroll
        for (int e = 0; e < 8; e++) p[e] += hv * wr[e * D_MODEL + d];
    }
    __shared__ float red[8][256];
#pragma unroll
    for (int e = 0; e < 8; e++) red[e][tid] = p[e];
    __syncthreads();
    for (int stp = 128; stp > 0; stp >>= 1) {
        if (tid < stp) {
#pragma unroll
            for (int e = 0; e < 8; e++) red[e][tid] += red[e][tid + stp];
        }
        __syncthreads();
    }
    if (tid == 0) {
        float lg[8];
        float m = -1e30f;
#pragma unroll
        for (int e = 0; e < 8; e++) { lg[e] = red[e][0]; m = fmaxf(m, lg[e]); }
        float pr[8];
#pragma unroll
        for (int e = 0; e < 8; e++) pr[e] = __expf(lg[e] - m);
        int i1 = 0;
#pragma unroll
        for (int e = 1; e < 8; e++) if (pr[e] > pr[i1]) i1 = e;
        int i2 = (i1 == 0) ? 1 : 0;
#pragma unroll
        for (int e = 0; e < 8; e++) if (e != i1 && pr[e] > pr[i2]) i2 = e;
        float v1 = pr[i1], v2 = pr[i2];
        float denom = v1 + v2;
        int pos1 = atomicAdd(&g_expcnt[i1], 1);
        g_toklist[i1 * LIST_STRIDE + pos1] = t * 2;
        g_entrygate[t * 2] = v1 / denom;
        int pos2 = atomicAdd(&g_expcnt[i2], 1);
        g_toklist[i2 * LIST_STRIDE + pos2] = t * 2 + 1;
        g_entrygate[t * 2 + 1] = v2 / denom;
    }
}

// ---------------- silu combine + split ----------------
__global__ void silu_split(const float* __restrict__ g, const float* __restrict__ u,
                           const float* __restrict__ eg, __nv_bfloat16* __restrict__ hi,
                           __nv_bfloat16* __restrict__ lo) {
    int entry = blockIdx.x;
    int tid = threadIdx.x;  // 256
    float gate = eg[entry];
    size_t base = (size_t)entry * NF;
#pragma unroll
    for (int j = 0; j < 4; j++) {
        int c = tid + j * 256;
        float gv = g[base + c];
        float uv = u[base + c];
        float a = gate * (gv / (1.f + __expf(-gv))) * uv;
        split_store(a, hi + base + c, lo + base + c);
    }
}

// ---------------- HMMA bf16x3 GEMM: C[M,N] = A @ B^T ----------------
// 256 threads / 8 warps. CTA tile M=128, N=128, BK=32. 3-stage cp.async pipeline.
// Warp tile 64x32 (warp grid 2x4). 3 MMA terms: Ah*Bh + Ah*Bl + Al*Bh.
// mode 0: dense (optional resid/aux).  mode 1: MoE gather (A row = entry>>1, C row = entry).
// mode 2: MoE down (A row = entry, atomicAdd into C row = entry>>1).
#define STAGE_BYTES 32768
#define HM_SMEM (3 * STAGE_BYTES)

__device__ __forceinline__ uint32_t sw_addr(uint32_t base, int row, int kchunk) {
    return base + (uint32_t)(row * 64) + (uint32_t)((kchunk ^ ((row >> 1) & 3)) << 4);
}

__global__ __launch_bounds__(256) void hmma_gemm(
    const __nv_bfloat16* __restrict__ Ahi, const __nv_bfloat16* __restrict__ Alo,
    const __nv_bfloat16* __restrict__ Bhi, const __nv_bfloat16* __restrict__ Blo,
    float* __restrict__ C, int N, int K,
    const float* __restrict__ resid, float* __restrict__ aux, int mode) {
    extern __shared__ char dsm[];
    __shared__ int arowS[128];
    __shared__ int crowS[128];

    int tid = threadIdx.x;
    int n0 = blockIdx.x * 128;
    int mb = blockIdx.y * 128;
    int e = blockIdx.z;
    int cnt = 1 << 30;
    if (mode != 0) {
        cnt = g_expcnt[e];
        if (mb >= cnt) return;
        size_t boff = (size_t)e * N * K;
        Bhi += boff;
        Blo += boff;
    }
    if (tid < 128) {
        if (mode == 0) {
            arowS[tid] = mb + tid;
            crowS[tid] = mb + tid;
        } else {
            int idx = mb + tid;
            if (idx > cnt - 1) idx = cnt - 1;
            int entry = g_toklist[e * LIST_STRIDE + idx];
            crowS[tid] = entry;
            arowS[tid] = (mode == 1) ? (entry >> 1) : entry;
        }
    }
    __syncthreads();

    uint32_t sb = smem_u32(dsm);
    const __nv_bfloat16* mats[4] = {Ahi, Alo, Bhi, Blo};

    // --- tile loader: per stage 4 sub-tiles of 128x32 bf16 (8KB each) ---
    auto load_tile = [&](int stage, int k0) {
        uint32_t sbase = sb + (uint32_t)stage * STAGE_BYTES;
#pragma unroll
        for (int i = 0; i < 8; i++) {
            int ci = i * 256 + tid;
            int mat = ci >> 9;
            int idx = ci & 511;
            int r = idx >> 2, c = idx & 3;
            uint32_t dst = sw_addr(sbase + (uint32_t)mat * 8192u, r, c);
            int grow = (mat < 2) ? arowS[r] : (n0 + r);
            const __nv_bfloat16* src = mats[mat] + (size_t)grow * K + k0 + c * 8;
            cpa16(dst, src);
        }
        cp_commit();
    };

    int T = K >> 5;
    load_tile(0, 0);
    load_tile(1, 32);

    int warp = tid >> 5, lane = tid & 31;
    int wm = warp >> 2, wn = warp & 3;  // warp tile: rows wm*64, cols wn*32
    int q = lane >> 3, sub = lane & 7;

    float acc[4][4][4];
#pragma unroll
    for (int mi = 0; mi < 4; mi++)
#pragma unroll
        for (int nj = 0; nj < 4; nj++)
#pragma unroll
            for (int v = 0; v < 4; v++) acc[mi][nj][v] = 0.f;

    for (int kt = 0; kt < T; kt++) {
        if (kt + 2 < T) load_tile((kt + 2) % 3, (kt + 2) * 32);
        if (kt + 2 < T) cp_wait2(); else cp_wait0();
        __syncthreads();
        uint32_t sbase = sb + (uint32_t)(kt % 3) * STAGE_BYTES;
        uint32_t aH = sbase, aL = sbase + 8192u, bH = sbase + 16384u, bL = sbase + 24576u;
#pragma unroll
        for (int ks = 0; ks < 2; ks++) {
            uint32_t ah[4][4], al[4][4], bh[2][4], bl[2][4];
            // A fragments: matrix q -> (row block q&1, kchunk q>>1)
#pragma unroll
            for (int mi = 0; mi < 4; mi++) {
                int row = wm * 64 + mi * 16 + (q & 1) * 8 + sub;
                int kc = ks * 2 + (q >> 1);
                ldsm_x4(ah[mi], sw_addr(aH, row, kc));
                ldsm_x4(al[mi], sw_addr(aL, row, kc));
            }
            // B fragments: matrix q -> (n block q>>1, kchunk q&1)
#pragma unroll
            for (int gj = 0; gj < 2; gj++) {
                int row = wn * 32 + gj * 16 + (q >> 1) * 8 + sub;
                int kc = ks * 2 + (q & 1);
                ldsm_x4(bh[gj], sw_addr(bH, row, kc));
                ldsm_x4(bl[gj], sw_addr(bL, row, kc));
            }
#pragma unroll
            for (int mi = 0; mi < 4; mi++)
#pragma unroll
                for (int nj = 0; nj < 4; nj++) {
                    const uint32_t* ph = &bh[nj >> 1][(nj & 1) * 2];
                    const uint32_t* pl = &bl[nj >> 1][(nj & 1) * 2];
                    mma_16816(acc[mi][nj], ah[mi], ph);
                    mma_16816(acc[mi][nj], ah[mi], pl);
                    mma_16816(acc[mi][nj], al[mi], ph);
                }
        }
        __syncthreads();
    }

    // ---------------- epilogue: direct fragment stores ----------------
    int qr = lane >> 2, qc = lane & 3;
#pragma unroll
    for (int mi = 0; mi < 4; mi++) {
#pragma unroll
        for (int half = 0; half < 2; half++) {
            int rl = wm * 64 + mi * 16 + half * 8 + qr;
            bool valid = (mode == 0) || (mb + rl < cnt);
            if (!valid) continue;
            size_t grow;
            if (mode == 0) grow = (size_t)(mb + rl);
            else if (mode == 1) grow = (size_t)crowS[rl];
            else grow = (size_t)(crowS[rl] >> 1);
            size_t gbase = grow * N + n0 + wn * 32 + qc * 2;
#pragma unroll
            for (int nj = 0; nj < 4; nj++) {
                float v0 = acc[mi][nj][half * 2 + 0];
                float v1 = acc[mi][nj][half * 2 + 1];
                size_t addr = gbase + nj * 8;
                if (mode == 2) {
                    atomicAdd(&C[addr + 0], v0);
                    atomicAdd(&C[addr + 1], v1);
                } else {
                    if (resid) {
                        v0 += resid[addr + 0];
                        v1 += resid[addr + 1];
                    }
                    float2 st = make_float2(v0, v1);
                    *(float2*)&C[addr] = st;
                    if (aux) *(float2*)&aux[addr] = st;
                }
            }
        }
    }
}

// ---------------- host launch ----------------
extern "C" void kernel_launch(void* const* d_in, const int* in_sizes, int n_in,
                              void* d_out, int out_size) {
    const float* x          = (const float*)d_in[0];
    const float* wattn_norm = (const float*)d_in[1];
    const float* wq         = (const float*)d_in[2];
    const float* wk         = (const float*)d_in[3];
    const float* wv         = (const float*)d_in[4];
    const float* wq_norm    = (const float*)d_in[5];
    const float* wk_norm    = (const float*)d_in[6];
    const float* wattn_out  = (const float*)d_in[7];
    const float* wffn_norm  = (const float*)d_in[8];
    const float* w_router   = (const float*)d_in[9];
    const float* w_gate     = (const float*)d_in[10];
    const float* w_up       = (const float*)d_in[11];
    const float* w_down     = (const float*)d_in[12];
    float* out = (float*)d_out;

    cudaFuncSetAttribute(hmma_gemm, cudaFuncAttributeMaxDynamicSharedMemorySize, HM_SMEM);

    float *p_q, *p_k, *p_v, *p_x2, *p_h2, *p_actg, *p_actu, *p_eg;
    cudaGetSymbolAddress((void**)&p_q, g_q);
    cudaGetSymbolAddress((void**)&p_k, g_k);
    cudaGetSymbolAddress((void**)&p_v, g_v);
    cudaGetSymbolAddress((void**)&p_x2, g_x2);
    cudaGetSymbolAddress((void**)&p_h2, g_h2);
    cudaGetSymbolAddress((void**)&p_actg, g_actg);
    cudaGetSymbolAddress((void**)&p_actu, g_actu);
    cudaGetSymbolAddress((void**)&p_eg, g_entrygate);

    __nv_bfloat16 *hh, *hl, *h2h, *h2l, *oh, *ol, *ah, *al;
    __nv_bfloat16 *wqh, *wql, *wkh, *wkl, *wvh, *wvl, *woh, *wol;
    __nv_bfloat16 *wgh, *wgl, *wuh, *wul, *wdh, *wdl;
    cudaGetSymbolAddress((void**)&hh, g_h_hi);   cudaGetSymbolAddress((void**)&hl, g_h_lo);
    cudaGetSymbolAddress((void**)&h2h, g_h2_hi); cudaGetSymbolAddress((void**)&h2l, g_h2_lo);
    cudaGetSymbolAddress((void**)&oh, g_o_hi);   cudaGetSymbolAddress((void**)&ol, g_o_lo);
    cudaGetSymbolAddress((void**)&ah, g_act_hi); cudaGetSymbolAddress((void**)&al, g_act_lo);
    cudaGetSymbolAddress((void**)&wqh, g_wq_hi); cudaGetSymbolAddress((void**)&wql, g_wq_lo);
    cudaGetSymbolAddress((void**)&wkh, g_wk_hi); cudaGetSymbolAddress((void**)&wkl, g_wk_lo);
    cudaGetSymbolAddress((void**)&wvh, g_wv_hi); cudaGetSymbolAddress((void**)&wvl, g_wv_lo);
    cudaGetSymbolAddress((void**)&woh, g_wo_hi); cudaGetSymbolAddress((void**)&wol, g_wo_lo);
    cudaGetSymbolAddress((void**)&wgh, g_wg_hi); cudaGetSymbolAddress((void**)&wgl, g_wg_lo);
    cudaGetSymbolAddress((void**)&wuh, g_wu_hi); cudaGetSymbolAddress((void**)&wul, g_wu_lo);
    cudaGetSymbolAddress((void**)&wdh, g_wd_hi); cudaGetSymbolAddress((void**)&wdl, g_wd_lo);

    // weight splits
    split_kernel<<<1024, 256>>>(wq, wqh, wql, 2048 * 2048);
    split_kernel<<<256, 256>>>(wk, wkh, wkl, 512 * 2048);
    split_kernel<<<256, 256>>>(wv, wvh, wvl, 512 * 2048);
    split_kernel<<<1024, 256>>>(wattn_out, woh, wol, 2048 * 2048);
    split_kernel<<<2048, 256>>>(w_gate, wgh, wgl, NE * NF * D_MODEL);
    split_kernel<<<2048, 256>>>(w_up, wuh, wul, NE * NF * D_MODEL);
    split_kernel<<<2048, 256>>>(w_down, wdh, wdl, NE * D_MODEL * NF);

    // 1. h = rmsnorm(x)
    rmsnorm_split<<<T_TOK, 256>>>(x, wattn_norm, nullptr, hh, hl);
    // 2. q/k/v projections (tensor cores via mma.sync)
    hmma_gemm<<<dim3(16, 32, 1), 256, HM_SMEM>>>(hh, hl, wqh, wql, p_q, 2048, 2048, nullptr, nullptr, 0);
    hmma_gemm<<<dim3(4, 32, 1), 256, HM_SMEM>>>(hh, hl, wkh, wkl, p_k, 512, 2048, nullptr, nullptr, 0);
    hmma_gemm<<<dim3(4, 32, 1), 256, HM_SMEM>>>(hh, hl, wvh, wvl, p_v, 512, 2048, nullptr, nullptr, 0);
    // 3. qk norm + rope
    qknorm_rope<<<T_TOK * NH, 128>>>(p_q, wq_norm, NH);
    qknorm_rope<<<T_TOK * NKV, 128>>>(p_k, wk_norm, NKV);
    // 4. attention -> o split
    attn_kernel<<<dim3(32, NH, 2), 128>>>(p_q, p_k, p_v, oh, ol);
    // 5. out projection + residual (writes g_x2 and d_out)
    hmma_gemm<<<dim3(16, 32, 1), 256, HM_SMEM>>>(oh, ol, woh, wol, p_x2, 2048, 2048, x, out, 0);
    // 6. h2 = rmsnorm(x2)  (fp32 for router + split for GEMMs)
    rmsnorm_split<<<T_TOK, 256>>>(p_x2, wffn_norm, p_h2, h2h, h2l);
    // 7. router
    zero_cnt_kernel<<<1, NE>>>();
    router_kernel<<<T_TOK, 256>>>(p_h2, w_router);
    // 8. MoE gate / up projections (gathered)
    hmma_gemm<<<dim3(8, 64, NE), 256, HM_SMEM>>>(h2h, h2l, wgh, wgl, p_actg, NF, 2048, nullptr, nullptr, 1);
    hmma_gemm<<<dim3(8, 64, NE), 256, HM_SMEM>>>(h2h, h2l, wuh, wul, p_actu, NF, 2048, nullptr, nullptr, 1);
    // 9. silu combine (+router gate) -> act split
    silu_split<<<2 * T_TOK, 256>>>(p_actg, p_actu, p_eg, ah, al);
    // 10. down projection, scatter-add into out
    hmma_gemm<<<dim3(16, 64, NE), 256, HM_SMEM>>>(ah, al, wdh, wdl, out, D_MODEL, NF, nullptr, nullptr, 2);
}

// round 7
// speedup vs baseline: 3.1208x; 1.7737x over previous
#include <cuda_runtime.h>
#include <cuda_bf16.h>
#include <math.h>
#include <stdint.h>

#define T_TOK 4096
#define D_MODEL 2048
#define S_SEQ 2048
#define NH 16
#define NKV 4
#define HDIM 128
#define NE 8
#define NF 1024
#define LIST_STRIDE (2 * T_TOK)

// ---------------- scratch (static device allocations; no cudaMalloc) ----------------
__device__ float g_q  [T_TOK * NH * HDIM];
__device__ float g_k  [T_TOK * NKV * HDIM];
__device__ float g_x2 [T_TOK * D_MODEL];
__device__ float g_h2 [T_TOK * D_MODEL];
__device__ float g_actg[T_TOK * 2 * NF];
__device__ float g_actu[T_TOK * 2 * NF];
__device__ int   g_toklist[NE * LIST_STRIDE];
__device__ float g_entrygate[2 * T_TOK];
__device__ int   g_expcnt[NE];

// bf16 hi/lo split buffers
__device__ __nv_bfloat16 g_h_hi [T_TOK * D_MODEL],  g_h_lo [T_TOK * D_MODEL];
__device__ __nv_bfloat16 g_h2_hi[T_TOK * D_MODEL],  g_h2_lo[T_TOK * D_MODEL];
__device__ __nv_bfloat16 g_o_hi [T_TOK * D_MODEL],  g_o_lo [T_TOK * D_MODEL];
__device__ __nv_bfloat16 g_k_hi [T_TOK * NKV * HDIM], g_k_lo [T_TOK * NKV * HDIM];
__device__ __nv_bfloat16 g_v_hi [T_TOK * NKV * HDIM], g_v_lo [T_TOK * NKV * HDIM];
__device__ __nv_bfloat16 g_act_hi[T_TOK * 2 * NF],  g_act_lo[T_TOK * 2 * NF];
__device__ __nv_bfloat16 g_wq_hi[2048 * 2048], g_wq_lo[2048 * 2048];
__device__ __nv_bfloat16 g_wk_hi[512 * 2048],  g_wk_lo[512 * 2048];
__device__ __nv_bfloat16 g_wv_hi[512 * 2048],  g_wv_lo[512 * 2048];
__device__ __nv_bfloat16 g_wo_hi[2048 * 2048], g_wo_lo[2048 * 2048];
__device__ __nv_bfloat16 g_wg_hi[NE * NF * D_MODEL], g_wg_lo[NE * NF * D_MODEL];
__device__ __nv_bfloat16 g_wu_hi[NE * NF * D_MODEL], g_wu_lo[NE * NF * D_MODEL];
__device__ __nv_bfloat16 g_wd_hi[NE * D_MODEL * NF], g_wd_lo[NE * D_MODEL * NF];

// ---------------- PTX helpers ----------------
__device__ __forceinline__ uint32_t smem_u32(const void* p) {
    return (uint32_t)__cvta_generic_to_shared(p);
}
__device__ __forceinline__ void cpa16(uint32_t dst, const void* src) {
    asm volatile("cp.async.cg.shared.global [%0], [%1], 16;" :: "r"(dst), "l"(src));
}
__device__ __forceinline__ void cp_commit() { asm volatile("cp.async.commit_group;" ::: "memory"); }
__device__ __forceinline__ void cp_wait2()  { asm volatile("cp.async.wait_group 2;" ::: "memory"); }
__device__ __forceinline__ void cp_wait1()  { asm volatile("cp.async.wait_group 1;" ::: "memory"); }
__device__ __forceinline__ void cp_wait0()  { asm volatile("cp.async.wait_group 0;" ::: "memory"); }

__device__ __forceinline__ void ldsm_x4(uint32_t r[4], uint32_t addr) {
    asm volatile("ldmatrix.sync.aligned.m8n8.x4.shared.b16 {%0,%1,%2,%3}, [%4];"
                 : "=r"(r[0]), "=r"(r[1]), "=r"(r[2]), "=r"(r[3]) : "r"(addr));
}
__device__ __forceinline__ void ldsm_x4_t(uint32_t r[4], uint32_t addr) {
    asm volatile("ldmatrix.sync.aligned.m8n8.x4.trans.shared.b16 {%0,%1,%2,%3}, [%4];"
                 : "=r"(r[0]), "=r"(r[1]), "=r"(r[2]), "=r"(r[3]) : "r"(addr));
}
__device__ __forceinline__ void mma_16816(float acc[4], const uint32_t a[4], const uint32_t b[2]) {
    asm volatile(
        "mma.sync.aligned.m16n8k16.row.col.f32.bf16.bf16.f32 "
        "{%0,%1,%2,%3}, {%4,%5,%6,%7}, {%8,%9}, {%0,%1,%2,%3};"
        : "+f"(acc[0]), "+f"(acc[1]), "+f"(acc[2]), "+f"(acc[3])
        : "r"(a[0]), "r"(a[1]), "r"(a[2]), "r"(a[3]), "r"(b[0]), "r"(b[1]));
}
__device__ __forceinline__ void split_store(float v, __nv_bfloat16* hp, __nv_bfloat16* lp) {
    __nv_bfloat16 h = __float2bfloat16_rn(v);
    *hp = h;
    *lp = __float2bfloat16_rn(v - __bfloat162float(h));
}
// aliasing-free bf16x2 -> u32 pack
__device__ __forceinline__ uint32_t bf2u(__nv_bfloat162 h) {
    uint32_t u;
    asm("mov.b32 %0, {%1, %2};" : "=r"(u)
        : "h"(__bfloat16_as_ushort(h.x)), "h"(__bfloat16_as_ushort(h.y)));
    return u;
}

// ---------------- fp32 -> bf16 hi/lo split (weights, vectorized) ----------------
__global__ void split_kernel(const float4* __restrict__ s, __nv_bfloat162* __restrict__ hi,
                             __nv_bfloat162* __restrict__ lo, int n4) {
    int i = blockIdx.x * blockDim.x + threadIdx.x;
    int stride = gridDim.x * blockDim.x;
    for (; i < n4; i += stride) {
        float4 v = s[i];
        __nv_bfloat162 h0 = __floats2bfloat162_rn(v.x, v.y);
        __nv_bfloat162 h1 = __floats2bfloat162_rn(v.z, v.w);
        hi[i * 2 + 0] = h0;
        hi[i * 2 + 1] = h1;
        lo[i * 2 + 0] = __floats2bfloat162_rn(v.x - __bfloat162float(h0.x),
                                              v.y - __bfloat162float(h0.y));
        lo[i * 2 + 1] = __floats2bfloat162_rn(v.z - __bfloat162float(h1.x),
                                              v.w - __bfloat162float(h1.y));
    }
}

// ---------------- rmsnorm + split ----------------
__global__ void rmsnorm_split(const float* __restrict__ x, const float* __restrict__ w,
                              float* __restrict__ outf, __nv_bfloat16* __restrict__ hi,
                              __nv_bfloat16* __restrict__ lo) {
    int row = blockIdx.x;
    int tid = threadIdx.x;  // 256
    const float* xr = x + (size_t)row * D_MODEL;
    float xv[8];
    float ss = 0.f;
#pragma unroll
    for (int i = 0; i < 8; i++) {
        xv[i] = xr[tid + i * 256];
        ss += xv[i] * xv[i];
    }
#pragma unroll
    for (int o = 16; o > 0; o >>= 1) ss += __shfl_xor_sync(0xffffffffu, ss, o);
    __shared__ float sred[8];
    if ((tid & 31) == 0) sred[tid >> 5] = ss;
    __syncthreads();
    float tot = 0.f;
#pragma unroll
    for (int i = 0; i < 8; i++) tot += sred[i];
    float rs = rsqrtf(tot / (float)D_MODEL + 1e-6f);
    size_t base = (size_t)row * D_MODEL;
#pragma unroll
    for (int i = 0; i < 8; i++) {
        int d = tid + i * 256;
        float v = xv[i] * rs * w[d];
        if (outf) outf[base + d] = v;
        split_store(v, hi + base + d, lo + base + d);
    }
}

// ---------------- per-head rmsnorm + RoPE ----------------
__global__ void qknorm_rope(float* __restrict__ data, const float* __restrict__ w, int nheads,
                            __nv_bfloat16* __restrict__ hi, __nv_bfloat16* __restrict__ lo) {
    int gb = blockIdx.x;
    int t = gb / nheads;
    int h = gb - t * nheads;
    int tid = threadIdx.x;  // 128
    size_t off = ((size_t)t * nheads + h) * HDIM;
    float* ptr = data + off;
    float v = ptr[tid];
    float ss = v * v;
#pragma unroll
    for (int o = 16; o > 0; o >>= 1) ss += __shfl_xor_sync(0xffffffffu, ss, o);
    __shared__ float sred[4];
    __shared__ float buf[HDIM];
    if ((tid & 31) == 0) sred[tid >> 5] = ss;
    __syncthreads();
    float tot = sred[0] + sred[1] + sred[2] + sred[3];
    float rs = rsqrtf(tot / 128.f + 1e-6f);
    buf[tid] = v * rs * w[tid];
    __syncthreads();
    int s = t & (S_SEQ - 1);
    int i = tid & 63;
    float fi = exp2f(-(float)i * 0.20762050592154265f);
    float ang = (float)s * fi;
    float sn, cs;
    sincosf(ang, &sn, &cs);
    float x1 = buf[i];
    float x2 = buf[i + 64];
    float outv = (tid < 64) ? (x1 * cs - x2 * sn) : (x1 * sn + x2 * cs);
    if (hi) {
        split_store(outv, hi + off + tid, lo + off + tid);
    } else {
        ptr[tid] = outv;
    }
}

// ---------------- HMMA causal flash attention ----------------
// grid (16, NH, B), 256 threads (8 warps). BM=128 q rows, BN=64 keys.
#define AT_SMEM (65536 + 2 * 65536)

__device__ __forceinline__ uint32_t tile_addr(uint32_t base, int row, int chunk) {
    return base + (uint32_t)(row * 256) + (uint32_t)((chunk ^ (row & 7)) << 4);
}

__global__ __launch_bounds__(256, 1) void attn_hmma(
    const float* __restrict__ Q,
    const __nv_bfloat16* __restrict__ Kh, const __nv_bfloat16* __restrict__ Kl,
    const __nv_bfloat16* __restrict__ Vh, const __nv_bfloat16* __restrict__ Vl,
    __nv_bfloat16* __restrict__ Ohi, __nv_bfloat16* __restrict__ Olo) {
    extern __shared__ char dsm[];
    uint32_t sb = smem_u32(dsm);
    const uint32_t Qh_s = sb, Ql_s = sb + 32768u;
    int qb = 15 - (int)blockIdx.x;
    int h = blockIdx.y, b = blockIdx.z;
    int tid = threadIdx.x;
    int w = tid >> 5, lane = tid & 31;
    int kvh = h >> 2;
    int qg = lane >> 3, sub = lane & 7;
    int qr = lane >> 2, qc2 = (lane & 3) * 2;
    const float e2 = 0.12751743f;  // log2(e)/sqrt(128)

    // ---- load FULL Q tile [128 x 128] fp32 -> split bf16 smem (16384 elems) ----
#pragma unroll
    for (int i = 0; i < 16; i++) {
        int idx = i * 256 + tid;           // 0..4095
        int row = idx >> 5;                // 0..127
        int d4 = (idx & 31) * 4;           // 0..124, 4 dims per thread
        const float4 v = *(const float4*)&Q[(((size_t)(b * S_SEQ + qb * 128 + row) * NH + h) << 7) + d4];
        __nv_bfloat162 h0 = __floats2bfloat162_rn(v.x, v.y);
        __nv_bfloat162 h1 = __floats2bfloat162_rn(v.z, v.w);
        __nv_bfloat162 l0v = __floats2bfloat162_rn(v.x - __bfloat162float(h0.x),
                                                   v.y - __bfloat162float(h0.y));
        __nv_bfloat162 l1v = __floats2bfloat162_rn(v.z - __bfloat162float(h1.x),
                                                   v.w - __bfloat162float(h1.y));
        uint32_t a = (uint32_t)(row * 256 + (((d4 >> 3) ^ (row & 7)) << 4) + (d4 & 7) * 2);
        *(__nv_bfloat162*)(dsm + a) = h0;
        *(__nv_bfloat162*)(dsm + a + 4) = h1;
        *(__nv_bfloat162*)(dsm + 32768 + a) = l0v;
        *(__nv_bfloat162*)(dsm + 32768 + a + 4) = l1v;
    }

    // ---- K/V tile prefetch ----
    auto prefetch = [&](int kb, int buf) {
        uint32_t base = sb + 65536u + (uint32_t)buf * 65536u;
#pragma unroll
        for (int i = 0; i < 16; i++) {
            int ci = i * 256 + tid;
            int mat = ci >> 10;
            int idx = ci & 1023;
            int row = idx >> 4, chunk = idx & 15;
            uint32_t dst = tile_addr(base + (uint32_t)mat * 16384u, row, chunk);
            size_t goff = (((size_t)(b * S_SEQ + kb * 64 + row) * NKV + kvh) << 7) + chunk * 8;
            const __nv_bfloat16* src;
            if (mat == 0) src = Kh + goff;
            else if (mat == 1) src = Kl + goff;
            else if (mat == 2) src = Vh + goff;
            else src = Vl + goff;
            cpa16(dst, src);
        }
        cp_commit();
    };

    float Oa[16][4];
#pragma unroll
    for (int d = 0; d < 16; d++)
#pragma unroll
        for (int j = 0; j < 4; j++) Oa[d][j] = 0.f;
    float m0 = -1e30f, m1 = -1e30f, l0 = 0.f, l1 = 0.f;

    int nkb = 2 * qb + 2;
    __syncthreads();
    prefetch(0, 0);

    for (int kb = 0; kb < nkb; kb++) {
        if (kb + 1 < nkb) {
            prefetch(kb + 1, (kb + 1) & 1);
            cp_wait1();
        } else {
            cp_wait0();
        }
        __syncthreads();
        uint32_t kv = sb + 65536u + (uint32_t)(kb & 1) * 65536u;
        uint32_t Kh_t = kv, Kl_t = kv + 16384u, Vh_t = kv + 32768u, Vl_t = kv + 49152u;

        // ---- S = Q K^T ----
        float s[8][4];
#pragma unroll
        for (int nb = 0; nb < 8; nb++)
#pragma unroll
            for (int j = 0; j < 4; j++) s[nb][j] = 0.f;

#pragma unroll
        for (int kc = 0; kc < 8; kc++) {
            uint32_t ah[4], al[4];
            int arow = w * 16 + (qg & 1) * 8 + sub;
            int achk = kc * 2 + (qg >> 1);
            ldsm_x4(ah, tile_addr(Qh_s, arow, achk));
            ldsm_x4(al, tile_addr(Ql_s, arow, achk));
#pragma unroll
            for (int nbp = 0; nbp < 4; nbp++) {
                uint32_t bh[4], bl[4];
                int brow = nbp * 16 + (qg >> 1) * 8 + sub;
                int bchk = kc * 2 + (qg & 1);
                ldsm_x4(bh, tile_addr(Kh_t, brow, bchk));
                ldsm_x4(bl, tile_addr(Kl_t, brow, bchk));
                mma_16816(s[2 * nbp + 0], ah, bh + 0);
                mma_16816(s[2 * nbp + 0], ah, bl + 0);
                mma_16816(s[2 * nbp + 0], al, bh + 0);
                mma_16816(s[2 * nbp + 1], ah, bh + 2);
                mma_16816(s[2 * nbp + 1], ah, bl + 2);
                mma_16816(s[2 * nbp + 1], al, bh + 2);
            }
        }

        // ---- mask + online softmax ----
        int row0 = qb * 128 + w * 16 + qr;
        int row1 = row0 + 8;
        if (kb >= 2 * qb) {
            int colb = kb * 64 + qc2;
#pragma unroll
            for (int nb = 0; nb < 8; nb++) {
                int c0 = colb + nb * 8, c1 = c0 + 1;
                if (c0 > row0) s[nb][0] = -1e30f;
                if (c1 > row0) s[nb][1] = -1e30f;
                if (c0 > row1) s[nb][2] = -1e30f;
                if (c1 > row1) s[nb][3] = -1e30f;
            }
        }
        float mx0 = -1e30f, mx1 = -1e30f;
#pragma unroll
        for (int nb = 0; nb < 8; nb++) {
            mx0 = fmaxf(mx0, fmaxf(s[nb][0], s[nb][1]));
            mx1 = fmaxf(mx1, fmaxf(s[nb][2], s[nb][3]));
        }
        mx0 = fmaxf(mx0, __shfl_xor_sync(0xffffffffu, mx0, 1));
        mx0 = fmaxf(mx0, __shfl_xor_sync(0xffffffffu, mx0, 2));
        mx1 = fmaxf(mx1, __shfl_xor_sync(0xffffffffu, mx1, 1));
        mx1 = fmaxf(mx1, __shfl_xor_sync(0xffffffffu, mx1, 2));
        float mn0 = fmaxf(m0, mx0), mn1 = fmaxf(m1, mx1);
        float f0 = exp2f((m0 - mn0) * e2), f1 = exp2f((m1 - mn1) * e2);
        m0 = mn0; m1 = mn1;
        l0 *= f0; l1 *= f1;
#pragma unroll
        for (int d = 0; d < 16; d++) {
            Oa[d][0] *= f0; Oa[d][1] *= f0;
            Oa[d][2] *= f1; Oa[d][3] *= f1;
        }
#pragma unroll
        for (int nb = 0; nb < 8; nb++) {
            s[nb][0] = exp2f((s[nb][0] - mn0) * e2);
            s[nb][1] = exp2f((s[nb][1] - mn0) * e2);
            s[nb][2] = exp2f((s[nb][2] - mn1) * e2);
            s[nb][3] = exp2f((s[nb][3] - mn1) * e2);
            l0 += s[nb][0] + s[nb][1];
            l1 += s[nb][2] + s[nb][3];
        }

        // ---- O += P V ----
#pragma unroll
        for (int kk = 0; kk < 4; kk++) {
            uint32_t ph[4], pl[4];
            float* p0 = s[2 * kk];
            float* p1 = s[2 * kk + 1];
            __nv_bfloat162 h00 = __floats2bfloat162_rn(p0[0], p0[1]);
            __nv_bfloat162 h01 = __floats2bfloat162_rn(p0[2], p0[3]);
            __nv_bfloat162 h10 = __floats2bfloat162_rn(p1[0], p1[1]);
            __nv_bfloat162 h11 = __floats2bfloat162_rn(p1[2], p1[3]);
            ph[0] = bf2u(h00); ph[1] = bf2u(h01);
            ph[2] = bf2u(h10); ph[3] = bf2u(h11);
            pl[0] = bf2u(__floats2bfloat162_rn(p0[0] - __bfloat162float(h00.x),
                                               p0[1] - __bfloat162float(h00.y)));
            pl[1] = bf2u(__floats2bfloat162_rn(p0[2] - __bfloat162float(h01.x),
                                               p0[3] - __bfloat162float(h01.y)));
            pl[2] = bf2u(__floats2bfloat162_rn(p1[0] - __bfloat162float(h10.x),
                                               p1[1] - __bfloat162float(h10.y)));
            pl[3] = bf2u(__floats2bfloat162_rn(p1[2] - __bfloat162float(h11.x),
                                               p1[3] - __bfloat162float(h11.y)));
#pragma unroll
            for (int dbp = 0; dbp < 8; dbp++) {
                uint32_t vh[4], vl[4];
                int vrow = kk * 16 + (qg & 1) * 8 + sub;
                int vchk = dbp * 2 + (qg >> 1);
                ldsm_x4_t(vh, tile_addr(Vh_t, vrow, vchk));
                ldsm_x4_t(vl, tile_addr(Vl_t, vrow, vchk));
                mma_16816(Oa[2 * dbp + 0], ph, vh + 0);
                mma_16816(Oa[2 * dbp + 0], ph, vl + 0);
                mma_16816(Oa[2 * dbp + 0], pl, vh + 0);
                mma_16816(Oa[2 * dbp + 1], ph, vh + 2);
                mma_16816(Oa[2 * dbp + 1], ph, vl + 2);
                mma_16816(Oa[2 * dbp + 1], pl, vh + 2);
            }
        }
        __syncthreads();
    }

    // ---- finalize ----
    l0 += __shfl_xor_sync(0xffffffffu, l0, 1);
    l0 += __shfl_xor_sync(0xffffffffu, l0, 2);
    l1 += __shfl_xor_sync(0xffffffffu, l1, 1);
    l1 += __shfl_xor_sync(0xffffffffu, l1, 2);
    float i0 = 1.f / l0, i1 = 1.f / l1;
    int row0 = qb * 128 + w * 16 + qr;
#pragma unroll
    for (int db = 0; db < 16; db++) {
        int col = h * 128 + db * 8 + qc2;
        size_t a0 = ((size_t)(b * S_SEQ + row0) << 11) + col;
        size_t a1 = ((size_t)(b * S_SEQ + row0 + 8) << 11) + col;
        float v0 = Oa[db][0] * i0, v1 = Oa[db][1] * i0;
        float v2 = Oa[db][2] * i1, v3 = Oa[db][3] * i1;
        __nv_bfloat162 h0 = __floats2bfloat162_rn(v0, v1);
        __nv_bfloat162 h1 = __floats2bfloat162_rn(v2, v3);
        *(__nv_bfloat162*)&Ohi[a0] = h0;
        *(__nv_bfloat162*)&Ohi[a1] = h1;
        *(__nv_bfloat162*)&Olo[a0] = __floats2bfloat162_rn(v0 - __bfloat162float(h0.x),
                                                           v1 - __bfloat162float(h0.y));
        *(__nv_bfloat162*)&Olo[a1] = __floats2bfloat162_rn(v2 - __bfloat162float(h1.x),
                                                           v3 - __bfloat162float(h1.y));
    }
}

// ---------------- router ----------------
__global__ void zero_cnt_kernel() { g_expcnt[threadIdx.x] = 0; }

__global__ void router_kernel(const float* __restrict__ h2, const float* __restrict__ wr) {
    int t = blockIdx.x;
    int tid = threadIdx.x;  // 256
    float p[8];
#pragma unroll
    for (int e = 0; e < 8; e++) p[e] = 0.f;
#pragma unroll
    for (int i = 0; i < 8; i++) {
        int d = tid + i * 256;
        float hv = h2[(size_t)t * D_MODEL + d];
#pragma unroll
        for (int e = 0; e < 8; e++) p[e] += hv * wr[e * D_MODEL + d];
    }
    __shared__ float red[8][256];
#pragma unroll
    for (int e = 0; e < 8; e++) red[e][tid] = p[e];
    __syncthreads();
    for (int stp = 128; stp > 0; stp >>= 1) {
        if (tid < stp) {
#pragma unroll
            for (int e = 0; e < 8; e++) red[e][tid] += red[e][tid + stp];
        }
        __syncthreads();
    }
    if (tid == 0) {
        float lg[8];
        float m = -1e30f;
#pragma unroll
        for (int e = 0; e < 8; e++) { lg[e] = red[e][0]; m = fmaxf(m, lg[e]); }
        float pr[8];
#pragma unroll
        for (int e = 0; e < 8; e++) pr[e] = __expf(lg[e] - m);
        int i1 = 0;
#pragma unroll
        for (int e = 1; e < 8; e++) if (pr[e] > pr[i1]) i1 = e;
        int i2 = (i1 == 0) ? 1 : 0;
#pragma unroll
        for (int e = 0; e < 8; e++) if (e != i1 && pr[e] > pr[i2]) i2 = e;
        float v1 = pr[i1], v2 = pr[i2];
        float denom = v1 + v2;
        int pos1 = atomicAdd(&g_expcnt[i1], 1);
        g_toklist[i1 * LIST_STRIDE + pos1] = t * 2;
        g_entrygate[t * 2] = v1 / denom;
        int pos2 = atomicAdd(&g_expcnt[i2], 1);
        g_toklist[i2 * LIST_STRIDE + pos2] = t * 2 + 1;
        g_entrygate[t * 2 + 1] = v2 / denom;
    }
}

// ---------------- silu combine + split ----------------
__global__ void silu_split(const float* __restrict__ g, const float* __restrict__ u,
                           const float* __restrict__ eg, __nv_bfloat16* __restrict__ hi,
                           __nv_bfloat16* __restrict__ lo) {
    int entry = blockIdx.x;
    int tid = threadIdx.x;  // 256
    float gate = eg[entry];
    size_t base = (size_t)entry * NF;
#pragma unroll
    for (int j = 0; j < 4; j++) {
        int c = tid + j * 256;
        float gv = g[base + c];
        float uv = u[base + c];
        float a = gate * (gv / (1.f + __expf(-gv))) * uv;
        split_store(a, hi + base + c, lo + base + c);
    }
}

// ---------------- HMMA bf16x3 GEMM: C[M,N] = A @ B^T ----------------
#define STAGE_BYTES 32768
#define HM_SMEM (3 * STAGE_BYTES)

__device__ __forceinline__ uint32_t sw_addr(uint32_t base, int row, int kchunk) {
    return base + (uint32_t)(row * 64) + (uint32_t)((kchunk ^ ((row >> 1) & 3)) << 4);
}

__global__ __launch_bounds__(256) void hmma_gemm(
    const __nv_bfloat16* __restrict__ Ahi, const __nv_bfloat16* __restrict__ Alo,
    const __nv_bfloat16* __restrict__ Bhi, const __nv_bfloat16* __restrict__ Blo,
    float* __restrict__ C, int N, int K,
    const float* __restrict__ resid, float* __restrict__ aux,
    __nv_bfloat16* __restrict__ Chi, __nv_bfloat16* __restrict__ Clo, int mode) {
    extern __shared__ char dsm[];
    __shared__ int arowS[128];
    __shared__ int crowS[128];

    int tid = threadIdx.x;
    int n0 = blockIdx.x * 128;
    int mb = blockIdx.y * 128;
    int e = blockIdx.z;
    int cnt = 1 << 30;
    if (mode == 1 || mode == 2) {
        cnt = g_expcnt[e];
        if (mb >= cnt) return;
        size_t boff = (size_t)e * N * K;
        Bhi += boff;
        Blo += boff;
    }
    if (tid < 128) {
        if (mode == 1 || mode == 2) {
            int idx = mb + tid;
            if (idx > cnt - 1) idx = cnt - 1;
            int entry = g_toklist[e * LIST_STRIDE + idx];
            crowS[tid] = entry;
            arowS[tid] = (mode == 1) ? (entry >> 1) : entry;
        } else {
            arowS[tid] = mb + tid;
            crowS[tid] = mb + tid;
        }
    }
    __syncthreads();

    uint32_t sb = smem_u32(dsm);
    const __nv_bfloat16* mats[4] = {Ahi, Alo, Bhi, Blo};

    auto load_tile = [&](int stage, int k0) {
        uint32_t sbase = sb + (uint32_t)stage * STAGE_BYTES;
#pragma unroll
        for (int i = 0; i < 8; i++) {
            int ci = i * 256 + tid;
            int mat = ci >> 9;
            int idx = ci & 511;
            int r = idx >> 2, c = idx & 3;
            uint32_t dst = sw_addr(sbase + (uint32_t)mat * 8192u, r, c);
            int grow = (mat < 2) ? arowS[r] : (n0 + r);
            const __nv_bfloat16* src = mats[mat] + (size_t)grow * K + k0 + c * 8;
            cpa16(dst, src);
        }
        cp_commit();
    };

    int T = K >> 5;
    load_tile(0, 0);
    load_tile(1, 32);

    int warp = tid >> 5, lane = tid & 31;
    int wm = warp >> 2, wn = warp & 3;
    int q = lane >> 3, sub = lane & 7;

    float acc[4][4][4];
#pragma unroll
    for (int mi = 0; mi < 4; mi++)
#pragma unroll
        for (int nj = 0; nj < 4; nj++)
#pragma unroll
            for (int v = 0; v < 4; v++) acc[mi][nj][v] = 0.f;

    for (int kt = 0; kt < T; kt++) {
        if (kt + 2 < T) load_tile((kt + 2) % 3, (kt + 2) * 32);
        if (kt + 2 < T) cp_wait2(); else cp_wait0();
        __syncthreads();
        uint32_t sbase = sb + (uint32_t)(kt % 3) * STAGE_BYTES;
        uint32_t aH = sbase, aL = sbase + 8192u, bH = sbase + 16384u, bL = sbase + 24576u;
#pragma unroll
        for (int ks = 0; ks < 2; ks++) {
            uint32_t ah[4][4], al[4][4], bh[2][4], bl[2][4];
#pragma unroll
            for (int mi = 0; mi < 4; mi++) {
                int row = wm * 64 + mi * 16 + (q & 1) * 8 + sub;
                int kc = ks * 2 + (q >> 1);
                ldsm_x4(ah[mi], sw_addr(aH, row, kc));
                ldsm_x4(al[mi], sw_addr(aL, row, kc));
            }
#pragma unroll
            for (int gj = 0; gj < 2; gj++) {
                int row = wn * 32 + gj * 16 + (q >> 1) * 8 + sub;
                int kc = ks * 2 + (q & 1);
                ldsm_x4(bh[gj], sw_addr(bH, row, kc));
                ldsm_x4(bl[gj], sw_addr(bL, row, kc));
            }
#pragma unroll
            for (int mi = 0; mi < 4; mi++)
#pragma unroll
                for (int nj = 0; nj < 4; nj++) {
                    const uint32_t* ph = &bh[nj >> 1][(nj & 1) * 2];
                    const uint32_t* pl = &bl[nj >> 1][(nj & 1) * 2];
                    mma_16816(acc[mi][nj], ah[mi], ph);
                    mma_16816(acc[mi][nj], ah[mi], pl);
                    mma_16816(acc[mi][nj], al[mi], ph);
                }
        }
        __syncthreads();
    }

    int qr = lane >> 2, qc = lane & 3;
#pragma unroll
    for (int mi = 0; mi < 4; mi++) {
#pragma unroll
        for (int half = 0; half < 2; half++) {
            int rl = wm * 64 + mi * 16 + half * 8 + qr;
            bool valid = (mode == 0) || (mode == 3) || (mb + rl < cnt);
            if (!valid) continue;
            size_t grow;
            if (mode == 1) grow = (size_t)crowS[rl];
            else if (mode == 2) grow = (size_t)(crowS[rl] >> 1);
            else grow = (size_t)(mb + rl);
            size_t gbase = grow * N + n0 + wn * 32 + qc * 2;
#pragma unroll
            for (int nj = 0; nj < 4; nj++) {
                float v0 = acc[mi][nj][half * 2 + 0];
                float v1 = acc[mi][nj][half * 2 + 1];
                size_t addr = gbase + nj * 8;
                if (mode == 2) {
                    atomicAdd(&C[addr + 0], v0);
                    atomicAdd(&C[addr + 1], v1);
                } else if (mode == 3) {
                    __nv_bfloat162 hv = __floats2bfloat162_rn(v0, v1);
                    *(__nv_bfloat162*)&Chi[addr] = hv;
                    *(__nv_bfloat162*)&Clo[addr] =
                        __floats2bfloat162_rn(v0 - __bfloat162float(hv.x),
                                              v1 - __bfloat162float(hv.y));
                } else {
                    if (resid) {
                        v0 += resid[addr + 0];
                        v1 += resid[addr + 1];
                    }
                    float2 st = make_float2(v0, v1);
                    *(float2*)&C[addr] = st;
                    if (aux) *(float2*)&aux[addr] = st;
                }
            }
        }
    }
}

// ---------------- host launch ----------------
extern "C" void kernel_launch(void* const* d_in, const int* in_sizes, int n_in,
                              void* d_out, int out_size) {
    const float* x          = (const float*)d_in[0];
    const float* wattn_norm = (const float*)d_in[1];
    const float* wq         = (const float*)d_in[2];
    const float* wk         = (const float*)d_in[3];
    const float* wv         = (const float*)d_in[4];
    const float* wq_norm    = (const float*)d_in[5];
    const float* wk_norm    = (const float*)d_in[6];
    const float* wattn_out  = (const float*)d_in[7];
    const float* wffn_norm  = (const float*)d_in[8];
    const float* w_router   = (const float*)d_in[9];
    const float* w_gate     = (const float*)d_in[10];
    const float* w_up       = (const float*)d_in[11];
    const float* w_down     = (const float*)d_in[12];
    float* out = (float*)d_out;

    cudaFuncSetAttribute(hmma_gemm, cudaFuncAttributeMaxDynamicSharedMemorySize, HM_SMEM);
    cudaFuncSetAttribute(attn_hmma, cudaFuncAttributeMaxDynamicSharedMemorySize, AT_SMEM);

    float *p_q, *p_k, *p_x2, *p_h2, *p_actg, *p_actu, *p_eg;
    cudaGetSymbolAddress((void**)&p_q, g_q);
    cudaGetSymbolAddress((void**)&p_k, g_k);
    cudaGetSymbolAddress((void**)&p_x2, g_x2);
    cudaGetSymbolAddress((void**)&p_h2, g_h2);
    cudaGetSymbolAddress((void**)&p_actg, g_actg);
    cudaGetSymbolAddress((void**)&p_actu, g_actu);
    cudaGetSymbolAddress((void**)&p_eg, g_entrygate);

    __nv_bfloat16 *hh, *hl, *h2h, *h2l, *oh, *ol, *ah, *al;
    __nv_bfloat16 *kh_, *kl_, *vh_, *vl_;
    __nv_bfloat16 *wqh, *wql, *wkh, *wkl, *wvh, *wvl, *woh, *wol;
    __nv_bfloat16 *wgh, *wgl, *wuh, *wul, *wdh, *wdl;
    cudaGetSymbolAddress((void**)&hh, g_h_hi);   cudaGetSymbolAddress((void**)&hl, g_h_lo);
    cudaGetSymbolAddress((void**)&h2h, g_h2_hi); cudaGetSymbolAddress((void**)&h2l, g_h2_lo);
    cudaGetSymbolAddress((void**)&oh, g_o_hi);   cudaGetSymbolAddress((void**)&ol, g_o_lo);
    cudaGetSymbolAddress((void**)&ah, g_act_hi); cudaGetSymbolAddress((void**)&al, g_act_lo);
    cudaGetSymbolAddress((void**)&kh_, g_k_hi);  cudaGetSymbolAddress((void**)&kl_, g_k_lo);
    cudaGetSymbolAddress((void**)&vh_, g_v_hi);  cudaGetSymbolAddress((void**)&vl_, g_v_lo);
    cudaGetSymbolAddress((void**)&wqh, g_wq_hi); cudaGetSymbolAddress((void**)&wql, g_wq_lo);
    cudaGetSymbolAddress((void**)&wkh, g_wk_hi); cudaGetSymbolAddress((void**)&wkl, g_wk_lo);
    cudaGetSymbolAddress((void**)&wvh, g_wv_hi); cudaGetSymbolAddress((void**)&wvl, g_wv_lo);
    cudaGetSymbolAddress((void**)&woh, g_wo_hi); cudaGetSymbolAddress((void**)&wol, g_wo_lo);
    cudaGetSymbolAddress((void**)&wgh, g_wg_hi); cudaGetSymbolAddress((void**)&wgl, g_wg_lo);
    cudaGetSymbolAddress((void**)&wuh, g_wu_hi); cudaGetSymbolAddress((void**)&wul, g_wu_lo);
    cudaGetSymbolAddress((void**)&wdh, g_wd_hi); cudaGetSymbolAddress((void**)&wdl, g_wd_lo);

    // weight splits (float4-vectorized)
    split_kernel<<<512, 256>>>((const float4*)wq, (__nv_bfloat162*)wqh, (__nv_bfloat162*)wql, 2048 * 512);
    split_kernel<<<128, 256>>>((const float4*)wk, (__nv_bfloat162*)wkh, (__nv_bfloat162*)wkl, 512 * 512);
    split_kernel<<<128, 256>>>((const float4*)wv, (__nv_bfloat162*)wvh, (__nv_bfloat162*)wvl, 512 * 512);
    split_kernel<<<512, 256>>>((const float4*)wattn_out, (__nv_bfloat162*)woh, (__nv_bfloat162*)wol, 2048 * 512);
    split_kernel<<<1024, 256>>>((const float4*)w_gate, (__nv_bfloat162*)wgh, (__nv_bfloat162*)wgl, NE * NF * 512);
    split_kernel<<<1024, 256>>>((const float4*)w_up, (__nv_bfloat162*)wuh, (__nv_bfloat162*)wul, NE * NF * 512);
    split_kernel<<<1024, 256>>>((const float4*)w_down, (__nv_bfloat162*)wdh, (__nv_bfloat162*)wdl, NE * D_MODEL * 256);

    // 1. h = rmsnorm(x)
    rmsnorm_split<<<T_TOK, 256>>>(x, wattn_norm, nullptr, hh, hl);
    // 2. q/k/v projections (V writes bf16 split directly)
    hmma_gemm<<<dim3(16, 32, 1), 256, HM_SMEM>>>(hh, hl, wqh, wql, p_q, 2048, 2048, nullptr, nullptr, nullptr, nullptr, 0);
    hmma_gemm<<<dim3(4, 32, 1), 256, HM_SMEM>>>(hh, hl, wkh, wkl, p_k, 512, 2048, nullptr, nullptr, nullptr, nullptr, 0);
    hmma_gemm<<<dim3(4, 32, 1), 256, HM_SMEM>>>(hh, hl, wvh, wvl, nullptr, 512, 2048, nullptr, nullptr, vh_, vl_, 3);
    // 3. qk norm + rope (Q in-place fp32; K -> bf16 split)
    qknorm_rope<<<T_TOK * NH, 128>>>(p_q, wq_norm, NH, nullptr, nullptr);
    qknorm_rope<<<T_TOK * NKV, 128>>>(p_k, wk_norm, NKV, kh_, kl_);
    // 4. HMMA flash attention -> o split
    attn_hmma<<<dim3(16, NH, 2), 256, AT_SMEM>>>(p_q, kh_, kl_, vh_, vl_, oh, ol);
    // 5. out projection + residual (writes g_x2 and d_out)
    hmma_gemm<<<dim3(16, 32, 1), 256, HM_SMEM>>>(oh, ol, woh, wol, p_x2, 2048, 2048, x, out, nullptr, nullptr, 0);
    // 6. h2 = rmsnorm(x2)
    rmsnorm_split<<<T_TOK, 256>>>(p_x2, wffn_norm, p_h2, h2h, h2l);
    // 7. router
    zero_cnt_kernel<<<1, NE>>>();
    router_kernel<<<T_TOK, 256>>>(p_h2, w_router);
    // 8. MoE gate / up projections (gathered)
    hmma_gemm<<<dim3(8, 64, NE), 256, HM_SMEM>>>(h2h, h2l, wgh, wgl, p_actg, NF, 2048, nullptr, nullptr, nullptr, nullptr, 1);
    hmma_gemm<<<dim3(8, 64, NE), 256, HM_SMEM>>>(h2h, h2l, wuh, wul, p_actu, NF, 2048, nullptr, nullptr, nullptr, nullptr, 1);
    // 9. silu combine (+router gate) -> act split
    silu_split<<<2 * T_TOK, 256>>>(p_actg, p_actu, p_eg, ah, al);
    // 10. down projection, scatter-add into out
    hmma_gemm<<<dim3(16, 64, NE), 256, HM_SMEM>>>(ah, al, wdh, wdl, out, D_MODEL, NF, nullptr, nullptr, nullptr, nullptr, 2);
}

// round 8
// speedup vs baseline: 3.6332x; 1.1642x over previous
#include <cuda_runtime.h>
#include <cuda_bf16.h>
#include <math.h>
#include <stdint.h>

#define T_TOK 4096
#define D_MODEL 2048
#define S_SEQ 2048
#define NH 16
#define NKV 4
#define HDIM 128
#define NE 8
#define NF 1024
#define LIST_STRIDE (2 * T_TOK)

// ---------------- scratch (static device allocations; no cudaMalloc) ----------------
__device__ float g_q  [T_TOK * NH * HDIM];
__device__ float g_k  [T_TOK * NKV * HDIM];
__device__ float g_x2 [T_TOK * D_MODEL];
__device__ float g_h2 [T_TOK * D_MODEL];
__device__ int   g_toklist[NE * LIST_STRIDE];
__device__ float g_entrygate[2 * T_TOK];
__device__ int   g_expcnt[NE];

// bf16 hi/lo split buffers
__device__ __nv_bfloat16 g_h_hi [T_TOK * D_MODEL],  g_h_lo [T_TOK * D_MODEL];
__device__ __nv_bfloat16 g_h2_hi[T_TOK * D_MODEL],  g_h2_lo[T_TOK * D_MODEL];
__device__ __nv_bfloat16 g_o_hi [T_TOK * D_MODEL],  g_o_lo [T_TOK * D_MODEL];
__device__ __nv_bfloat16 g_k_hi [T_TOK * NKV * HDIM], g_k_lo [T_TOK * NKV * HDIM];
__device__ __nv_bfloat16 g_v_hi [T_TOK * NKV * HDIM], g_v_lo [T_TOK * NKV * HDIM];
__device__ __nv_bfloat16 g_act_hi[T_TOK * 2 * NF],  g_act_lo[T_TOK * 2 * NF];
// packed QKV weights: rows 0..2047 wq, 2048..2559 wk, 2560..3071 wv
__device__ __nv_bfloat16 g_wqkv_hi[3072 * 2048], g_wqkv_lo[3072 * 2048];
__device__ __nv_bfloat16 g_wo_hi[2048 * 2048], g_wo_lo[2048 * 2048];
// interleaved gate/up: per expert 2048 rows, row 2f = wg[f], 2f+1 = wu[f]
__device__ __nv_bfloat16 g_wgu_hi[NE * 2048 * D_MODEL], g_wgu_lo[NE * 2048 * D_MODEL];
__device__ __nv_bfloat16 g_wd_hi[NE * D_MODEL * NF], g_wd_lo[NE * D_MODEL * NF];

// ---------------- PTX helpers ----------------
__device__ __forceinline__ uint32_t smem_u32(const void* p) {
    return (uint32_t)__cvta_generic_to_shared(p);
}
__device__ __forceinline__ void cpa16(uint32_t dst, const void* src) {
    asm volatile("cp.async.cg.shared.global [%0], [%1], 16;" :: "r"(dst), "l"(src));
}
__device__ __forceinline__ void cp_commit() { asm volatile("cp.async.commit_group;" ::: "memory"); }
__device__ __forceinline__ void cp_wait1()  { asm volatile("cp.async.wait_group 1;" ::: "memory"); }
__device__ __forceinline__ void cp_wait0()  { asm volatile("cp.async.wait_group 0;" ::: "memory"); }

__device__ __forceinline__ void ldsm_x4(uint32_t r[4], uint32_t addr) {
    asm volatile("ldmatrix.sync.aligned.m8n8.x4.shared.b16 {%0,%1,%2,%3}, [%4];"
                 : "=r"(r[0]), "=r"(r[1]), "=r"(r[2]), "=r"(r[3]) : "r"(addr));
}
__device__ __forceinline__ void ldsm_x4_t(uint32_t r[4], uint32_t addr) {
    asm volatile("ldmatrix.sync.aligned.m8n8.x4.trans.shared.b16 {%0,%1,%2,%3}, [%4];"
                 : "=r"(r[0]), "=r"(r[1]), "=r"(r[2]), "=r"(r[3]) : "r"(addr));
}
__device__ __forceinline__ void mma_16816(float acc[4], const uint32_t a[4], const uint32_t b[2]) {
    asm volatile(
        "mma.sync.aligned.m16n8k16.row.col.f32.bf16.bf16.f32 "
        "{%0,%1,%2,%3}, {%4,%5,%6,%7}, {%8,%9}, {%0,%1,%2,%3};"
        : "+f"(acc[0]), "+f"(acc[1]), "+f"(acc[2]), "+f"(acc[3])
        : "r"(a[0]), "r"(a[1]), "r"(a[2]), "r"(a[3]), "r"(b[0]), "r"(b[1]));
}
__device__ __forceinline__ void split_store(float v, __nv_bfloat16* hp, __nv_bfloat16* lp) {
    __nv_bfloat16 h = __float2bfloat16_rn(v);
    *hp = h;
    *lp = __float2bfloat16_rn(v - __bfloat162float(h));
}
__device__ __forceinline__ uint32_t bf2u(__nv_bfloat162 h) {
    uint32_t u;
    asm("mov.b32 %0, {%1, %2};" : "=r"(u)
        : "h"(__bfloat16_as_ushort(h.x)), "h"(__bfloat16_as_ushort(h.y)));
    return u;
}

// ---------------- fp32 -> bf16 hi/lo split (contiguous) ----------------
__global__ void split_kernel(const float4* __restrict__ s, __nv_bfloat162* __restrict__ hi,
                             __nv_bfloat162* __restrict__ lo, int n4) {
    int i = blockIdx.x * blockDim.x + threadIdx.x;
    int stride = gridDim.x * blockDim.x;
    for (; i < n4; i += stride) {
        float4 v = s[i];
        __nv_bfloat162 h0 = __floats2bfloat162_rn(v.x, v.y);
        __nv_bfloat162 h1 = __floats2bfloat162_rn(v.z, v.w);
        hi[i * 2 + 0] = h0;
        hi[i * 2 + 1] = h1;
        lo[i * 2 + 0] = __floats2bfloat162_rn(v.x - __bfloat162float(h0.x),
                                              v.y - __bfloat162float(h0.y));
        lo[i * 2 + 1] = __floats2bfloat162_rn(v.z - __bfloat162float(h1.x),
                                              v.w - __bfloat162float(h1.y));
    }
}

// ---------------- gate/up interleaving split: src (e,f,d) -> dst row e*2048 + 2f + sel ----
__global__ void split_interleave(const float4* __restrict__ s, __nv_bfloat162* __restrict__ hi,
                                 __nv_bfloat162* __restrict__ lo, int sel) {
    int n4 = NE * NF * (D_MODEL / 4);
    int i = blockIdx.x * blockDim.x + threadIdx.x;
    int stride = gridDim.x * blockDim.x;
    for (; i < n4; i += stride) {
        float4 v = s[i];
        int d4 = i & 511;              // (d/4)
        int fidx = i >> 9;             // e*NF + f
        int f = fidx & (NF - 1);
        int e = fidx >> 10;
        size_t dst2 = ((size_t)(e * 2048 + 2 * f + sel) * 512 + d4) * 2;
        __nv_bfloat162 h0 = __floats2bfloat162_rn(v.x, v.y);
        __nv_bfloat162 h1 = __floats2bfloat162_rn(v.z, v.w);
        hi[dst2 + 0] = h0;
        hi[dst2 + 1] = h1;
        lo[dst2 + 0] = __floats2bfloat162_rn(v.x - __bfloat162float(h0.x),
                                             v.y - __bfloat162float(h0.y));
        lo[dst2 + 1] = __floats2bfloat162_rn(v.z - __bfloat162float(h1.x),
                                             v.w - __bfloat162float(h1.y));
    }
}

// ---------------- rmsnorm + split ----------------
__global__ void rmsnorm_split(const float* __restrict__ x, const float* __restrict__ w,
                              float* __restrict__ outf, __nv_bfloat16* __restrict__ hi,
                              __nv_bfloat16* __restrict__ lo) {
    int row = blockIdx.x;
    int tid = threadIdx.x;  // 256
    const float* xr = x + (size_t)row * D_MODEL;
    float xv[8];
    float ss = 0.f;
#pragma unroll
    for (int i = 0; i < 8; i++) {
        xv[i] = xr[tid + i * 256];
        ss += xv[i] * xv[i];
    }
#pragma unroll
    for (int o = 16; o > 0; o >>= 1) ss += __shfl_xor_sync(0xffffffffu, ss, o);
    __shared__ float sred[8];
    if ((tid & 31) == 0) sred[tid >> 5] = ss;
    __syncthreads();
    float tot = 0.f;
#pragma unroll
    for (int i = 0; i < 8; i++) tot += sred[i];
    float rs = rsqrtf(tot / (float)D_MODEL + 1e-6f);
    size_t base = (size_t)row * D_MODEL;
#pragma unroll
    for (int i = 0; i < 8; i++) {
        int d = tid + i * 256;
        float v = xv[i] * rs * w[d];
        if (outf) outf[base + d] = v;
        split_store(v, hi + base + d, lo + base + d);
    }
}

// ---------------- per-head rmsnorm + RoPE: one WARP per head ----------------
// 256 threads = 8 heads/block. hi==null: write fp32 in place; else bf16 split.
__global__ void qknorm_rope(float* __restrict__ data, const float* __restrict__ w, int nheads,
                            __nv_bfloat16* __restrict__ hi, __nv_bfloat16* __restrict__ lo) {
    int gw = blockIdx.x * 8 + (threadIdx.x >> 5);
    int lane = threadIdx.x & 31;
    int t = gw / nheads;
    int h = gw - t * nheads;
    size_t off = ((size_t)t * nheads + h) * HDIM + lane * 4;
    float4 v = *(float4*)&data[off];
    float ss = v.x * v.x + v.y * v.y + v.z * v.z + v.w * v.w;
#pragma unroll
    for (int o = 16; o > 0; o >>= 1) ss += __shfl_xor_sync(0xffffffffu, ss, o);
    float rs = rsqrtf(ss * (1.f / 128.f) + 1e-6f);
    const float4 wv = *(const float4*)&w[lane * 4];
    v.x *= rs * wv.x; v.y *= rs * wv.y; v.z *= rs * wv.z; v.w *= rs * wv.w;
    // partner halves via shfl_xor 16 (dims d <-> d+64)
    float4 p;
    p.x = __shfl_xor_sync(0xffffffffu, v.x, 16);
    p.y = __shfl_xor_sync(0xffffffffu, v.y, 16);
    p.z = __shfl_xor_sync(0xffffffffu, v.z, 16);
    p.w = __shfl_xor_sync(0xffffffffu, v.w, 16);
    int s = t & (S_SEQ - 1);
    int ibase = (lane * 4) & 63;
    bool lohalf = lane < 16;
    float o4[4];
    float vv[4] = {v.x, v.y, v.z, v.w};
    float pp[4] = {p.x, p.y, p.z, p.w};
#pragma unroll
    for (int c = 0; c < 4; c++) {
        float fi = exp2f(-(float)(ibase + c) * 0.20762050592154265f);
        float ang = (float)s * fi;
        float sn, cs;
        sincosf(ang, &sn, &cs);
        // lo half holds x1 (v), partner is x2; hi half holds x2 (v), partner x1
        o4[c] = lohalf ? (vv[c] * cs - pp[c] * sn) : (pp[c] * sn + vv[c] * cs);
    }
    if (hi) {
#pragma unroll
        for (int c = 0; c < 4; c++) split_store(o4[c], hi + off + c, lo + off + c);
    } else {
        *(float4*)&data[off] = make_float4(o4[0], o4[1], o4[2], o4[3]);
    }
}

// ---------------- HMMA causal flash attention ----------------
#define AT_SMEM (65536 + 2 * 65536)

__device__ __forceinline__ uint32_t tile_addr(uint32_t base, int row, int chunk) {
    return base + (uint32_t)(row * 256) + (uint32_t)((chunk ^ (row & 7)) << 4);
}

__global__ __launch_bounds__(256, 1) void attn_hmma(
    const float* __restrict__ Q,
    const __nv_bfloat16* __restrict__ Kh, const __nv_bfloat16* __restrict__ Kl,
    const __nv_bfloat16* __restrict__ Vh, const __nv_bfloat16* __restrict__ Vl,
    __nv_bfloat16* __restrict__ Ohi, __nv_bfloat16* __restrict__ Olo) {
    extern __shared__ char dsm[];
    uint32_t sb = smem_u32(dsm);
    const uint32_t Qh_s = sb, Ql_s = sb + 32768u;
    int qb = 15 - (int)blockIdx.x;
    int h = blockIdx.y, b = blockIdx.z;
    int tid = threadIdx.x;
    int w = tid >> 5, lane = tid & 31;
    int kvh = h >> 2;
    int qg = lane >> 3, sub = lane & 7;
    int qr = lane >> 2, qc2 = (lane & 3) * 2;
    const float e2 = 0.12751743f;  // log2(e)/sqrt(128)

#pragma unroll
    for (int i = 0; i < 16; i++) {
        int idx = i * 256 + tid;
        int row = idx >> 5;
        int d4 = (idx & 31) * 4;
        const float4 v = *(const float4*)&Q[(((size_t)(b * S_SEQ + qb * 128 + row) * NH + h) << 7) + d4];
        __nv_bfloat162 h0 = __floats2bfloat162_rn(v.x, v.y);
        __nv_bfloat162 h1 = __floats2bfloat162_rn(v.z, v.w);
        __nv_bfloat162 l0v = __floats2bfloat162_rn(v.x - __bfloat162float(h0.x),
                                                   v.y - __bfloat162float(h0.y));
        __nv_bfloat162 l1v = __floats2bfloat162_rn(v.z - __bfloat162float(h1.x),
                                                   v.w - __bfloat162float(h1.y));
        uint32_t a = (uint32_t)(row * 256 + (((d4 >> 3) ^ (row & 7)) << 4) + (d4 & 7) * 2);
        *(__nv_bfloat162*)(dsm + a) = h0;
        *(__nv_bfloat162*)(dsm + a + 4) = h1;
        *(__nv_bfloat162*)(dsm + 32768 + a) = l0v;
        *(__nv_bfloat162*)(dsm + 32768 + a + 4) = l1v;
    }

    auto prefetch = [&](int kb, int buf) {
        uint32_t base = sb + 65536u + (uint32_t)buf * 65536u;
#pragma unroll
        for (int i = 0; i < 16; i++) {
            int ci = i * 256 + tid;
            int mat = ci >> 10;
            int idx = ci & 1023;
            int row = idx >> 4, chunk = idx & 15;
            uint32_t dst = tile_addr(base + (uint32_t)mat * 16384u, row, chunk);
            size_t goff = (((size_t)(b * S_SEQ + kb * 64 + row) * NKV + kvh) << 7) + chunk * 8;
            const __nv_bfloat16* src;
            if (mat == 0) src = Kh + goff;
            else if (mat == 1) src = Kl + goff;
            else if (mat == 2) src = Vh + goff;
            else src = Vl + goff;
            cpa16(dst, src);
        }
        cp_commit();
    };

    float Oa[16][4];
#pragma unroll
    for (int d = 0; d < 16; d++)
#pragma unroll
        for (int j = 0; j < 4; j++) Oa[d][j] = 0.f;
    float m0 = -1e30f, m1 = -1e30f, l0 = 0.f, l1 = 0.f;

    int nkb = 2 * qb + 2;
    prefetch(0, 0);

    for (int kb = 0; kb < nkb; kb++) {
        cp_wait0();
        __syncthreads();
        if (kb + 1 < nkb) prefetch(kb + 1, (kb + 1) & 1);
        uint32_t kv = sb + 65536u + (uint32_t)(kb & 1) * 65536u;
        uint32_t Kh_t = kv, Kl_t = kv + 16384u, Vh_t = kv + 32768u, Vl_t = kv + 49152u;

        float s[8][4];
#pragma unroll
        for (int nb = 0; nb < 8; nb++)
#pragma unroll
            for (int j = 0; j < 4; j++) s[nb][j] = 0.f;

#pragma unroll
        for (int kc = 0; kc < 8; kc++) {
            uint32_t ah[4], al[4];
            int arow = w * 16 + (qg & 1) * 8 + sub;
            int achk = kc * 2 + (qg >> 1);
            ldsm_x4(ah, tile_addr(Qh_s, arow, achk));
            ldsm_x4(al, tile_addr(Ql_s, arow, achk));
#pragma unroll
            for (int nbp = 0; nbp < 4; nbp++) {
                uint32_t bh[4], bl[4];
                int brow = nbp * 16 + (qg >> 1) * 8 + sub;
                int bchk = kc * 2 + (qg & 1);
                ldsm_x4(bh, tile_addr(Kh_t, brow, bchk));
                ldsm_x4(bl, tile_addr(Kl_t, brow, bchk));
                mma_16816(s[2 * nbp + 0], ah, bh + 0);
                mma_16816(s[2 * nbp + 0], ah, bl + 0);
                mma_16816(s[2 * nbp + 0], al, bh + 0);
                mma_16816(s[2 * nbp + 1], ah, bh + 2);
                mma_16816(s[2 * nbp + 1], ah, bl + 2);
                mma_16816(s[2 * nbp + 1], al, bh + 2);
            }
        }

        int row0 = qb * 128 + w * 16 + qr;
        int row1 = row0 + 8;
        if (kb >= 2 * qb) {
            int colb = kb * 64 + qc2;
#pragma unroll
            for (int nb = 0; nb < 8; nb++) {
                int c0 = colb + nb * 8, c1 = c0 + 1;
                if (c0 > row0) s[nb][0] = -1e30f;
                if (c1 > row0) s[nb][1] = -1e30f;
                if (c0 > row1) s[nb][2] = -1e30f;
                if (c1 > row1) s[nb][3] = -1e30f;
            }
        }
        float mx0 = -1e30f, mx1 = -1e30f;
#pragma unroll
        for (int nb = 0; nb < 8; nb++) {
            mx0 = fmaxf(mx0, fmaxf(s[nb][0], s[nb][1]));
            mx1 = fmaxf(mx1, fmaxf(s[nb][2], s[nb][3]));
        }
        mx0 = fmaxf(mx0, __shfl_xor_sync(0xffffffffu, mx0, 1));
        mx0 = fmaxf(mx0, __shfl_xor_sync(0xffffffffu, mx0, 2));
        mx1 = fmaxf(mx1, __shfl_xor_sync(0xffffffffu, mx1, 1));
        mx1 = fmaxf(mx1, __shfl_xor_sync(0xffffffffu, mx1, 2));
        float mn0 = fmaxf(m0, mx0), mn1 = fmaxf(m1, mx1);
        float f0 = exp2f((m0 - mn0) * e2), f1 = exp2f((m1 - mn1) * e2);
        m0 = mn0; m1 = mn1;
        l0 *= f0; l1 *= f1;
#pragma unroll
        for (int d = 0; d < 16; d++) {
            Oa[d][0] *= f0; Oa[d][1] *= f0;
            Oa[d][2] *= f1; Oa[d][3] *= f1;
        }
#pragma unroll
        for (int nb = 0; nb < 8; nb++) {
            s[nb][0] = exp2f((s[nb][0] - mn0) * e2);
            s[nb][1] = exp2f((s[nb][1] - mn0) * e2);
            s[nb][2] = exp2f((s[nb][2] - mn1) * e2);
            s[nb][3] = exp2f((s[nb][3] - mn1) * e2);
            l0 += s[nb][0] + s[nb][1];
            l1 += s[nb][2] + s[nb][3];
        }

#pragma unroll
        for (int kk = 0; kk < 4; kk++) {
            uint32_t ph[4], pl[4];
            float* p0 = s[2 * kk];
            float* p1 = s[2 * kk + 1];
            __nv_bfloat162 h00 = __floats2bfloat162_rn(p0[0], p0[1]);
            __nv_bfloat162 h01 = __floats2bfloat162_rn(p0[2], p0[3]);
            __nv_bfloat162 h10 = __floats2bfloat162_rn(p1[0], p1[1]);
            __nv_bfloat162 h11 = __floats2bfloat162_rn(p1[2], p1[3]);
            ph[0] = bf2u(h00); ph[1] = bf2u(h01);
            ph[2] = bf2u(h10); ph[3] = bf2u(h11);
            pl[0] = bf2u(__floats2bfloat162_rn(p0[0] - __bfloat162float(h00.x),
                                               p0[1] - __bfloat162float(h00.y)));
            pl[1] = bf2u(__floats2bfloat162_rn(p0[2] - __bfloat162float(h01.x),
                                               p0[3] - __bfloat162float(h01.y)));
            pl[2] = bf2u(__floats2bfloat162_rn(p1[0] - __bfloat162float(h10.x),
                                               p1[1] - __bfloat162float(h10.y)));
            pl[3] = bf2u(__floats2bfloat162_rn(p1[2] - __bfloat162float(h11.x),
                                               p1[3] - __bfloat162float(h11.y)));
#pragma unroll
            for (int dbp = 0; dbp < 8; dbp++) {
                uint32_t vh[4], vl[4];
                int vrow = kk * 16 + (qg & 1) * 8 + sub;
                int vchk = dbp * 2 + (qg >> 1);
                ldsm_x4_t(vh, tile_addr(Vh_t, vrow, vchk));
                ldsm_x4_t(vl, tile_addr(Vl_t, vrow, vchk));
                mma_16816(Oa[2 * dbp + 0], ph, vh + 0);
                mma_16816(Oa[2 * dbp + 0], ph, vl + 0);
                mma_16816(Oa[2 * dbp + 0], pl, vh + 0);
                mma_16816(Oa[2 * dbp + 1], ph, vh + 2);
                mma_16816(Oa[2 * dbp + 1], ph, vl + 2);
                mma_16816(Oa[2 * dbp + 1], pl, vh + 2);
            }
        }
    }

    l0 += __shfl_xor_sync(0xffffffffu, l0, 1);
    l0 += __shfl_xor_sync(0xffffffffu, l0, 2);
    l1 += __shfl_xor_sync(0xffffffffu, l1, 1);
    l1 += __shfl_xor_sync(0xffffffffu, l1, 2);
    float i0 = 1.f / l0, i1 = 1.f / l1;
    int row0 = qb * 128 + w * 16 + qr;
#pragma unroll
    for (int db = 0; db < 16; db++) {
        int col = h * 128 + db * 8 + qc2;
        size_t a0 = ((size_t)(b * S_SEQ + row0) << 11) + col;
        size_t a1 = ((size_t)(b * S_SEQ + row0 + 8) << 11) + col;
        float v0 = Oa[db][0] * i0, v1 = Oa[db][1] * i0;
        float v2 = Oa[db][2] * i1, v3 = Oa[db][3] * i1;
        __nv_bfloat162 h0 = __floats2bfloat162_rn(v0, v1);
        __nv_bfloat162 h1 = __floats2bfloat162_rn(v2, v3);
        *(__nv_bfloat162*)&Ohi[a0] = h0;
        *(__nv_bfloat162*)&Ohi[a1] = h1;
        *(__nv_bfloat162*)&Olo[a0] = __floats2bfloat162_rn(v0 - __bfloat162float(h0.x),
                                                           v1 - __bfloat162float(h0.y));
        *(__nv_bfloat162*)&Olo[a1] = __floats2bfloat162_rn(v2 - __bfloat162float(h1.x),
                                                           v3 - __bfloat162float(h1.y));
    }
}

// ---------------- router ----------------
__global__ void zero_cnt_kernel() { g_expcnt[threadIdx.x] = 0; }

__global__ void router_kernel(const float* __restrict__ h2, const float* __restrict__ wr) {
    int t = blockIdx.x;
    int tid = threadIdx.x;  // 256
    float p[8];
#pragma unroll
    for (int e = 0; e < 8; e++) p[e] = 0.f;
#pragma unroll
    for (int i = 0; i < 8; i++) {
        int d = tid + i * 256;
        float hv = h2[(size_t)t * D_MODEL + d];
#pragma unroll
        for (int e = 0; e < 8; e++) p[e] += hv * wr[e * D_MODEL + d];
    }
    __shared__ float red[8][256];
#pragma unroll
    for (int e = 0; e < 8; e++) red[e][tid] = p[e];
    __syncthreads();
    for (int stp = 128; stp > 0; stp >>= 1) {
        if (tid < stp) {
#pragma unroll
            for (int e = 0; e < 8; e++) red[e][tid] += red[e][tid + stp];
        }
        __syncthreads();
    }
    if (tid == 0) {
        float lg[8];
        float m = -1e30f;
#pragma unroll
        for (int e = 0; e < 8; e++) { lg[e] = red[e][0]; m = fmaxf(m, lg[e]); }
        float pr[8];
#pragma unroll
        for (int e = 0; e < 8; e++) pr[e] = __expf(lg[e] - m);
        int i1 = 0;
#pragma unroll
        for (int e = 1; e < 8; e++) if (pr[e] > pr[i1]) i1 = e;
        int i2 = (i1 == 0) ? 1 : 0;
#pragma unroll
        for (int e = 0; e < 8; e++) if (e != i1 && pr[e] > pr[i2]) i2 = e;
        float v1 = pr[i1], v2 = pr[i2];
        float denom = v1 + v2;
        int pos1 = atomicAdd(&g_expcnt[i1], 1);
        g_toklist[i1 * LIST_STRIDE + pos1] = t * 2;
        g_entrygate[t * 2] = v1 / denom;
        int pos2 = atomicAdd(&g_expcnt[i2], 1);
        g_toklist[i2 * LIST_STRIDE + pos2] = t * 2 + 1;
        g_entrygate[t * 2 + 1] = v2 / denom;
    }
}

// ---------------- HMMA bf16x3 GEMM: C[M,N] = A @ B^T ----------------
// modes: 0 dense fp32 (+resid/aux dup), 2 MoE-down atomic, 4 MoE gate/up interleaved
// + silu -> act split, 6 fused QKV epilogue (Q fp32 / K fp32 / V split).
#define STAGE_BYTES 32768
#define HM_SMEM (3 * STAGE_BYTES)

__device__ __forceinline__ uint32_t sw_addr(uint32_t base, int row, int kchunk) {
    return base + (uint32_t)(row * 64) + (uint32_t)((kchunk ^ ((row >> 1) & 3)) << 4);
}

__global__ __launch_bounds__(256) void hmma_gemm(
    const __nv_bfloat16* __restrict__ Ahi, const __nv_bfloat16* __restrict__ Alo,
    const __nv_bfloat16* __restrict__ Bhi, const __nv_bfloat16* __restrict__ Blo,
    float* __restrict__ C, int N, int K,
    const float* __restrict__ resid, float* __restrict__ aux, int mode) {
    extern __shared__ char dsm[];
    __shared__ int arowS[128];
    __shared__ int crowS[128];

    int tid = threadIdx.x;
    int n0 = blockIdx.x * 128;
    int mb = blockIdx.y * 128;
    int e = blockIdx.z;
    int cnt = 1 << 30;
    bool moe = (mode == 2 || mode == 4);
    if (moe) {
        cnt = g_expcnt[e];
        if (mb >= cnt) return;
        size_t boff = (size_t)e * N * K;
        Bhi += boff;
        Blo += boff;
    }
    if (tid < 128) {
        if (moe) {
            int idx = mb + tid;
            if (idx > cnt - 1) idx = cnt - 1;
            int entry = g_toklist[e * LIST_STRIDE + idx];
            crowS[tid] = entry;
            arowS[tid] = (mode == 4) ? (entry >> 1) : entry;
        } else {
            arowS[tid] = mb + tid;
            crowS[tid] = mb + tid;
        }
    }
    __syncthreads();

    uint32_t sb = smem_u32(dsm);
    const __nv_bfloat16* mats[4] = {Ahi, Alo, Bhi, Blo};

    auto load_tile = [&](int stage, int k0) {
        uint32_t sbase = sb + (uint32_t)stage * STAGE_BYTES;
#pragma unroll
        for (int i = 0; i < 8; i++) {
            int ci = i * 256 + tid;
            int mat = ci >> 9;
            int idx = ci & 511;
            int r = idx >> 2, c = idx & 3;
            uint32_t dst = sw_addr(sbase + (uint32_t)mat * 8192u, r, c);
            int grow = (mat < 2) ? arowS[r] : (n0 + r);
            const __nv_bfloat16* src = mats[mat] + (size_t)grow * K + k0 + c * 8;
            cpa16(dst, src);
        }
        cp_commit();
    };

    int T = K >> 5;
    load_tile(0, 0);
    load_tile(1, 32);

    int warp = tid >> 5, lane = tid & 31;
    int wm = warp >> 2, wn = warp & 3;
    int q = lane >> 3, sub = lane & 7;

    float acc[4][4][4];
#pragma unroll
    for (int mi = 0; mi < 4; mi++)
#pragma unroll
        for (int nj = 0; nj < 4; nj++)
#pragma unroll
            for (int v = 0; v < 4; v++) acc[mi][nj][v] = 0.f;

    for (int kt = 0; kt < T; kt++) {
        if (kt < T - 1) cp_wait1(); else cp_wait0();
        __syncthreads();
        if (kt + 2 < T) load_tile((kt + 2) % 3, (kt + 2) * 32);
        uint32_t sbase = sb + (uint32_t)(kt % 3) * STAGE_BYTES;
        uint32_t aH = sbase, aL = sbase + 8192u, bH = sbase + 16384u, bL = sbase + 24576u;
#pragma unroll
        for (int ks = 0; ks < 2; ks++) {
            uint32_t ah[4][4], al[4][4], bh[2][4], bl[2][4];
#pragma unroll
            for (int mi = 0; mi < 4; mi++) {
                int row = wm * 64 + mi * 16 + (q & 1) * 8 + sub;
                int kc = ks * 2 + (q >> 1);
                ldsm_x4(ah[mi], sw_addr(aH, row, kc));
                ldsm_x4(al[mi], sw_addr(aL, row, kc));
            }
#pragma unroll
            for (int gj = 0; gj < 2; gj++) {
                int row = wn * 32 + gj * 16 + (q >> 1) * 8 + sub;
                int kc = ks * 2 + (q & 1);
                ldsm_x4(bh[gj], sw_addr(bH, row, kc));
                ldsm_x4(bl[gj], sw_addr(bL, row, kc));
            }
#pragma unroll
            for (int mi = 0; mi < 4; mi++)
#pragma unroll
                for (int nj = 0; nj < 4; nj++) {
                    const uint32_t* ph = &bh[nj >> 1][(nj & 1) * 2];
                    const uint32_t* pl = &bl[nj >> 1][(nj & 1) * 2];
                    mma_16816(acc[mi][nj], ah[mi], ph);
                    mma_16816(acc[mi][nj], ah[mi], pl);
                    mma_16816(acc[mi][nj], al[mi], ph);
                }
        }
    }

    int qr = lane >> 2, qc = lane & 3;
#pragma unroll
    for (int mi = 0; mi < 4; mi++) {
#pragma unroll
        for (int half = 0; half < 2; half++) {
            int rl = wm * 64 + mi * 16 + half * 8 + qr;
            if (moe && mb + rl >= cnt) continue;
            if (mode == 6) {
                int grow = mb + rl;
#pragma unroll
                for (int nj = 0; nj < 4; nj++) {
                    float v0 = acc[mi][nj][half * 2 + 0];
                    float v1 = acc[mi][nj][half * 2 + 1];
                    int col = n0 + wn * 32 + qc * 2 + nj * 8;
                    if (n0 < 2048) {
                        *(float2*)&C[(size_t)grow * 2048 + col] = make_float2(v0, v1);
                    } else if (n0 < 2560) {
                        *(float2*)&g_k[(size_t)grow * 512 + col - 2048] = make_float2(v0, v1);
                    } else {
                        size_t a = (size_t)grow * 512 + col - 2560;
                        __nv_bfloat162 hv = __floats2bfloat162_rn(v0, v1);
                        *(__nv_bfloat162*)&g_v_hi[a] = hv;
                        *(__nv_bfloat162*)&g_v_lo[a] =
                            __floats2bfloat162_rn(v0 - __bfloat162float(hv.x),
                                                  v1 - __bfloat162float(hv.y));
                    }
                }
            } else if (mode == 4) {
                int entry = crowS[rl];
                float eg = g_entrygate[entry];
#pragma unroll
                for (int nj = 0; nj < 4; nj++) {
                    float gv = acc[mi][nj][half * 2 + 0];
                    float uv = acc[mi][nj][half * 2 + 1];
                    int f = (n0 + wn * 32 + qc * 2 + nj * 8) >> 1;
                    float a = eg * (gv / (1.f + __expf(-gv))) * uv;
                    size_t ai = (size_t)entry * NF + f;
                    split_store(a, g_act_hi + ai, g_act_lo + ai);
                }
            } else if (mode == 2) {
                size_t gbase = (size_t)(crowS[rl] >> 1) * N + n0 + wn * 32 + qc * 2;
#pragma unroll
                for (int nj = 0; nj < 4; nj++) {
                    atomicAdd(&C[gbase + nj * 8 + 0], acc[mi][nj][half * 2 + 0]);
                    atomicAdd(&C[gbase + nj * 8 + 1], acc[mi][nj][half * 2 + 1]);
                }
            } else {  // mode 0
                size_t gbase = (size_t)(mb + rl) * N + n0 + wn * 32 + qc * 2;
#pragma unroll
                for (int nj = 0; nj < 4; nj++) {
                    float v0 = acc[mi][nj][half * 2 + 0];
                    float v1 = acc[mi][nj][half * 2 + 1];
                    size_t addr = gbase + nj * 8;
                    if (resid) {
                        v0 += resid[addr + 0];
                        v1 += resid[addr + 1];
                    }
                    float2 st = make_float2(v0, v1);
                    *(float2*)&C[addr] = st;
                    if (aux) *(float2*)&aux[addr] = st;
                }
            }
        }
    }
}

// ---------------- host launch ----------------
extern "C" void kernel_launch(void* const* d_in, const int* in_sizes, int n_in,
                              void* d_out, int out_size) {
    const float* x          = (const float*)d_in[0];
    const float* wattn_norm = (const float*)d_in[1];
    const float* wq         = (const float*)d_in[2];
    const float* wk         = (const float*)d_in[3];
    const float* wv         = (const float*)d_in[4];
    const float* wq_norm    = (const float*)d_in[5];
    const float* wk_norm    = (const float*)d_in[6];
    const float* wattn_out  = (const float*)d_in[7];
    const float* wffn_norm  = (const float*)d_in[8];
    const float* w_router   = (const float*)d_in[9];
    const float* w_gate     = (const float*)d_in[10];
    const float* w_up       = (const float*)d_in[11];
    const float* w_down     = (const float*)d_in[12];
    float* out = (float*)d_out;

    cudaFuncSetAttribute(hmma_gemm, cudaFuncAttributeMaxDynamicSharedMemorySize, HM_SMEM);
    cudaFuncSetAttribute(attn_hmma, cudaFuncAttributeMaxDynamicSharedMemorySize, AT_SMEM);

    float *p_q, *p_k, *p_x2, *p_h2;
    cudaGetSymbolAddress((void**)&p_q, g_q);
    cudaGetSymbolAddress((void**)&p_k, g_k);
    cudaGetSymbolAddress((void**)&p_x2, g_x2);
    cudaGetSymbolAddress((void**)&p_h2, g_h2);

    __nv_bfloat16 *hh, *hl, *h2h, *h2l, *oh, *ol, *ah, *al;
    __nv_bfloat16 *kh_, *kl_, *vh_, *vl_;
    __nv_bfloat16 *wqkvh, *wqkvl, *woh, *wol, *wguh, *wgul, *wdh, *wdl;
    cudaGetSymbolAddress((void**)&hh, g_h_hi);   cudaGetSymbolAddress((void**)&hl, g_h_lo);
    cudaGetSymbolAddress((void**)&h2h, g_h2_hi); cudaGetSymbolAddress((void**)&h2l, g_h2_lo);
    cudaGetSymbolAddress((void**)&oh, g_o_hi);   cudaGetSymbolAddress((void**)&ol, g_o_lo);
    cudaGetSymbolAddress((void**)&ah, g_act_hi); cudaGetSymbolAddress((void**)&al, g_act_lo);
    cudaGetSymbolAddress((void**)&kh_, g_k_hi);  cudaGetSymbolAddress((void**)&kl_, g_k_lo);
    cudaGetSymbolAddress((void**)&vh_, g_v_hi);  cudaGetSymbolAddress((void**)&vl_, g_v_lo);
    cudaGetSymbolAddress((void**)&wqkvh, g_wqkv_hi); cudaGetSymbolAddress((void**)&wqkvl, g_wqkv_lo);
    cudaGetSymbolAddress((void**)&woh, g_wo_hi); cudaGetSymbolAddress((void**)&wol, g_wo_lo);
    cudaGetSymbolAddress((void**)&wguh, g_wgu_hi); cudaGetSymbolAddress((void**)&wgul, g_wgu_lo);
    cudaGetSymbolAddress((void**)&wdh, g_wd_hi); cudaGetSymbolAddress((void**)&wdl, g_wd_lo);

    // 0-2: QKV weight splits into packed buffer (rows 0..2047 / 2048..2559 / 2560..3071)
    split_kernel<<<512, 256>>>((const float4*)wq, (__nv_bfloat162*)wqkvh, (__nv_bfloat162*)wqkvl, 2048 * 512);
    split_kernel<<<128, 256>>>((const float4*)wk, (__nv_bfloat162*)(wqkvh + 2048 * 2048),
                               (__nv_bfloat162*)(wqkvl + 2048 * 2048), 512 * 512);
    split_kernel<<<128, 256>>>((const float4*)wv, (__nv_bfloat162*)(wqkvh + 2560 * 2048),
                               (__nv_bfloat162*)(wqkvl + 2560 * 2048), 512 * 512);
    // 3: h = rmsnorm(x)
    rmsnorm_split<<<T_TOK, 256>>>(x, wattn_norm, nullptr, hh, hl);
    // 4: wo split
    split_kernel<<<512, 256>>>((const float4*)wattn_out, (__nv_bfloat162*)woh, (__nv_bfloat162*)wol, 2048 * 512);
    // 5: fused QKV projection (ncu captures this launch)
    hmma_gemm<<<dim3(24, 32, 1), 256, HM_SMEM>>>(hh, hl, wqkvh, wqkvl, p_q, 3072, 2048, nullptr, nullptr, 6);
    // 6-7: qk norm + rope (warp-per-head)
    qknorm_rope<<<T_TOK * NH / 8, 256>>>(p_q, wq_norm, NH, nullptr, nullptr);
    qknorm_rope<<<T_TOK * NKV / 8, 256>>>(p_k, wk_norm, NKV, kh_, kl_);
    // 8: HMMA flash attention -> o split
    attn_hmma<<<dim3(16, NH, 2), 256, AT_SMEM>>>(p_q, kh_, kl_, vh_, vl_, oh, ol);
    // 9: out projection + residual (writes g_x2 and d_out)
    hmma_gemm<<<dim3(16, 32, 1), 256, HM_SMEM>>>(oh, ol, woh, wol, p_x2, 2048, 2048, x, out, 0);
    // 10: h2 = rmsnorm(x2)
    rmsnorm_split<<<T_TOK, 256>>>(p_x2, wffn_norm, p_h2, h2h, h2l);
    // 11-12: router
    zero_cnt_kernel<<<1, NE>>>();
    router_kernel<<<T_TOK, 256>>>(p_h2, w_router);
    // 13-15: MoE weight splits (gate/up interleaved, down contiguous)
    split_interleave<<<1024, 256>>>((const float4*)w_gate, (__nv_bfloat162*)wguh, (__nv_bfloat162*)wgul, 0);
    split_interleave<<<1024, 256>>>((const float4*)w_up, (__nv_bfloat162*)wguh, (__nv_bfloat162*)wgul, 1);
    split_kernel<<<1024, 256>>>((const float4*)w_down, (__nv_bfloat162*)wdh, (__nv_bfloat162*)wdl, NE * D_MODEL * 256);
    // 16: fused gate/up GEMM + silu + router gate -> act split
    hmma_gemm<<<dim3(16, 64, NE), 256, HM_SMEM>>>(h2h, h2l, wguh, wgul, nullptr, 2048, 2048, nullptr, nullptr, 4);
    // 17: down projection, scatter-add into out
    hmma_gemm<<<dim3(16, 64, NE), 256, HM_SMEM>>>(ah, al, wdh, wdl, out, D_MODEL, NF, nullptr, nullptr, 2);
}